// round 8
// baseline (speedup 1.0000x reference)
#include <cuda_runtime.h>
#include <math.h>

typedef unsigned long long u64;
typedef unsigned int u32;
#define NN 512
#define NH 4
#define MR (2*NN)

__device__ float g_q[MR*256];
__device__ float g_k[MR*256];
__device__ float g_v[MR*256];
__device__ float g_a[MR*256];
__device__ float g_b[MR*256];
__device__ __align__(16) float g_attn[(size_t)2*NH*NN*NN];  // [b][h][i][j]
__device__ float g_ctx[MR*256];

struct GCoef { float c[10]; };

__device__ __forceinline__ u64 pk(float lo, float hi) {
    u64 r; asm("mov.b64 %0,{%1,%2};" : "=l"(r) : "f"(lo), "f"(hi)); return r;
}
__device__ __forceinline__ void upk(u64 v, float& lo, float& hi) {
    asm("mov.b64 {%0,%1},%2;" : "=f"(lo), "=f"(hi) : "l"(v));
}
__device__ __forceinline__ u64 f2add(u64 a, u64 b) {
    u64 d; asm("add.rn.f32x2 %0,%1,%2;" : "=l"(d) : "l"(a), "l"(b)); return d;
}
__device__ __forceinline__ u64 f2fma(u64 a, u64 b, u64 c) {
    u64 d; asm("fma.rn.f32x2 %0,%1,%2,%3;" : "=l"(d) : "l"(a), "l"(b), "l"(c)); return d;
}
// un-hoistable shared load (keeps w2 out of the register file)
__device__ __forceinline__ void lds2u64(u64& a, u64& b, u32 addr) {
    asm volatile("ld.shared.v2.u64 {%0,%1},[%2];" : "=l"(a), "=l"(b) : "r"(addr));
}

// ---- 64x64 GEMM, K=256, 256 thr, 4x4/thread, FMA2, reg-double-buffered ----
__device__ __forceinline__ void gemm64(
    const float* __restrict__ A, const float* __restrict__ W,
    const float* __restrict__ bias, float* __restrict__ C,
    int m0, int n0)
{
    __shared__ __align__(16) float As[2][16][68];
    __shared__ __align__(16) float Ws[2][16][68];
    int tid = threadIdx.x, tx = tid & 15, ty = tid >> 4;
    u64 acc[4][2] = {};

    int ar = tid >> 2, ac = (tid & 3) * 4;
    int wk = tid >> 4, wn = (tid & 15) * 4;

    float4 pA = *(const float4*)&A[(m0 + ar) * 256 + ac];
    float4 pW = *(const float4*)&W[wk * 256 + n0 + wn];

    int buf = 0;
    for (int t = 0; t < 16; t++) {
        As[buf][ac+0][ar] = pA.x; As[buf][ac+1][ar] = pA.y;
        As[buf][ac+2][ar] = pA.z; As[buf][ac+3][ar] = pA.w;
        *(float4*)&Ws[buf][wk][wn] = pW;
        __syncthreads();
        if (t < 15) {
            int k0 = (t + 1) * 16;
            pA = *(const float4*)&A[(m0 + ar) * 256 + k0 + ac];
            pW = *(const float4*)&W[(k0 + wk) * 256 + n0 + wn];
        }
        #pragma unroll
        for (int kk = 0; kk < 16; kk++) {
            float4 ra = *(const float4*)&As[buf][kk][ty * 4];
            ulonglong2 wv = *(const ulonglong2*)&Ws[buf][kk][tx * 4];
            u64 r0 = pk(ra.x, ra.x), r1 = pk(ra.y, ra.y);
            u64 r2 = pk(ra.z, ra.z), r3 = pk(ra.w, ra.w);
            acc[0][0] = f2fma(r0, wv.x, acc[0][0]);
            acc[0][1] = f2fma(r0, wv.y, acc[0][1]);
            acc[1][0] = f2fma(r1, wv.x, acc[1][0]);
            acc[1][1] = f2fma(r1, wv.y, acc[1][1]);
            acc[2][0] = f2fma(r2, wv.x, acc[2][0]);
            acc[2][1] = f2fma(r2, wv.y, acc[2][1]);
            acc[3][0] = f2fma(r3, wv.x, acc[3][0]);
            acc[3][1] = f2fma(r3, wv.y, acc[3][1]);
        }
        buf ^= 1;
    }
    int n = n0 + tx * 4;
    float b0 = 0.f, b1 = 0.f, b2 = 0.f, b3 = 0.f;
    if (bias) { b0 = bias[n]; b1 = bias[n+1]; b2 = bias[n+2]; b3 = bias[n+3]; }
    #pragma unroll
    for (int i = 0; i < 4; i++) {
        float o0,o1,o2,o3;
        upk(acc[i][0], o0, o1); upk(acc[i][1], o2, o3);
        *(float4*)&C[(m0 + ty*4 + i) * 256 + n] =
            make_float4(o0 + b0, o1 + b1, o2 + b2, o3 + b3);
    }
}

__global__ __launch_bounds__(256) void k_proj(
    const float* __restrict__ x,
    const float* __restrict__ Wq, const float* __restrict__ bq,
    const float* __restrict__ Wk, const float* __restrict__ bk,
    const float* __restrict__ Wv, const float* __restrict__ bv,
    const float* __restrict__ Wp1, const float* __restrict__ bp1)
{
    int bn = blockIdx.x;
    int seg = bn >> 2, n0 = (bn & 3) * 64;
    const float* W; const float* bias; float* C;
    switch (seg) {
        case 0: W = Wq; bias = bq; C = g_q; break;
        case 1: W = Wk; bias = bk; C = g_k; break;
        case 2: W = Wv; bias = bv; C = g_v; break;
        case 3: W = Wp1; bias = nullptr; C = g_a; break;
        default: W = Wp1 + 256*256; bias = bp1; C = g_b; break;  // bp1 folded
    }
    gemm64(x, W, bias, C, blockIdx.y * 64, n0);
}

// ---------------- K2: fused pair scores (w2 in smem, 3 blocks/SM) ----------------
__global__ __launch_bounds__(256, 3) void k_scores(
    const int* __restrict__ adj, const float* __restrict__ Wp2,
    const float* __restrict__ bp2, GCoef co)
{
    int b = blockIdx.z, i0 = blockIdx.y * 8, j0base = blockIdx.x * 128;
    int tid = threadIdx.x, lane = tid & 31, w = tid >> 5;
    int h = lane >> 3;

    __shared__ __align__(16) float sA[8][256], sQ[8][256], sB[8][256], sK[8][256];
    __shared__ int sM[8][128];
    __shared__ __align__(16) u64 sW2[4][32][4];   // [p][lane][head], 0.5*Wp2 packed

    u64 C[10];
    #pragma unroll
    for (int kk = 0; kk < 10; kk++) C[kk] = pk(co.c[kk], co.c[kk]);
    const u64 K3 = pk(1.0f/3.0f, 1.0f/3.0f);
    const u64 KM1 = pk(-1.0f, -1.0f);
    const u64 KABS = 0x7FFFFFFF7FFFFFFFull;

    // build shared w2 table: entry (p, l, hh) = pk(0.5*Wp2[(l*8+2p)*4+hh], 0.5*Wp2[(l*8+2p+1)*4+hh])
    #pragma unroll
    for (int e = tid; e < 512; e += 256) {
        int p = e >> 7, l = (e >> 2) & 31, hh = e & 3;
        int c0 = l * 8 + 2 * p;
        sW2[p][l][hh] = pk(0.5f * Wp2[c0 * 4 + hh], 0.5f * Wp2[(c0 + 1) * 4 + hh]);
    }
    u32 w2base;
    {
        u64 gaddr = __cvta_generic_to_shared(&sW2[0][lane][0]);
        w2base = (u32)gaddr;
    }
    float myb = bp2[h];

    const float* aptr = g_a + (b * NN + i0) * 256;
    const float* qptr = g_q + (b * NN + i0) * 256;
    #pragma unroll
    for (int t = 0; t < 2; t++) {
        int idx = tid + t * 256;
        ((float4*)sA)[idx] = ((const float4*)aptr)[idx];
        ((float4*)sQ)[idx] = ((const float4*)qptr)[idx];
    }
    #pragma unroll
    for (int t = 0; t < 4; t++) {
        int idx = tid + t * 256;
        sM[idx >> 7][idx & 127] = adj[(i0 + (idx >> 7)) * NN + j0base + (idx & 127)];
    }

    for (int jc = 0; jc < 128; jc += 8) {
        int j0 = j0base + jc;
        __syncthreads();
        const float* bptr = g_b + (b * NN + j0) * 256;
        const float* kptr = g_k + (b * NN + j0) * 256;
        #pragma unroll
        for (int t = 0; t < 2; t++) {
            int idx = tid + t * 256;
            ((float4*)sB)[idx] = ((const float4*)bptr)[idx];
            ((float4*)sK)[idx] = ((const float4*)kptr)[idx];
        }
        __syncthreads();

        int j = j0 + w;
        u64 bbp[4], kvp[4];
        {
            ulonglong2 x0 = *(const ulonglong2*)&sB[w][lane*8];
            ulonglong2 x1 = *(const ulonglong2*)&sB[w][lane*8+4];
            bbp[0]=x0.x; bbp[1]=x0.y; bbp[2]=x1.x; bbp[3]=x1.y;
            ulonglong2 y0 = *(const ulonglong2*)&sK[w][lane*8];
            ulonglong2 y1 = *(const ulonglong2*)&sK[w][lane*8+4];
            kvp[0]=y0.x; kvp[1]=y0.y; kvp[2]=y1.x; kvp[3]=y1.y;
        }

        #pragma unroll
        for (int il = 0; il < 8; il++) {
            int mval = sM[il][jc + w];
            int i = i0 + il;
            float* outp = &g_attn[((size_t)(b * NH) * NN + i) * NN + j];
            if (mval == 0) {
                if ((lane & 7) == 0) outp[(size_t)h * NN * NN] = -1e9f;
                continue;
            }
            u64 aA[4], qA[4];
            {
                ulonglong2 x0 = *(const ulonglong2*)&sA[il][lane*8];
                ulonglong2 x1 = *(const ulonglong2*)&sA[il][lane*8+4];
                aA[0]=x0.x; aA[1]=x0.y; aA[2]=x1.x; aA[3]=x1.y;
                ulonglong2 y0 = *(const ulonglong2*)&sQ[il][lane*8];
                ulonglong2 y1 = *(const ulonglong2*)&sQ[il][lane*8+4];
                qA[0]=y0.x; qA[1]=y0.y; qA[2]=y1.x; qA[3]=y1.y;
            }
            u64 aw0=0, aw1=0, aw2=0, aw3=0, qk=0;
            #pragma unroll
            for (int p = 0; p < 4; p++) {
                u64 t = f2add(aA[p], bbp[p]);
                u64 m = t & KABS;
                u64 wv = f2fma(m, K3, KM1);
                u64 S = C[9];
                #pragma unroll
                for (int kk = 8; kk >= 0; kk--) S = f2fma(S, wv, C[kk]);
                u64 G = f2add(f2add(t, m), S);   // 2*gelu
                u64 wv0, wv1, wv2, wv3;
                lds2u64(wv0, wv1, w2base + p * 1024);
                lds2u64(wv2, wv3, w2base + p * 1024 + 16);
                aw0 = f2fma(G, wv0, aw0);
                aw1 = f2fma(G, wv1, aw1);
                aw2 = f2fma(G, wv2, aw2);
                aw3 = f2fma(G, wv3, aw3);
                qk  = f2fma(qA[p], kvp[p], qk);
            }
            float r0,r1,r2,r3,x0,x1,qx,qy;
            upk(aw0,r0,x0); r0+=x0;
            upk(aw1,r1,x1); r1+=x1;
            upk(aw2,r2,x0); r2+=x0;
            upk(aw3,r3,x1); r3+=x1;
            upk(qk,qx,qy);
            float qs = (qx+qy)*0.125f;
            if (h==0) r0+=qs; else if (h==1) r1+=qs; else if (h==2) r2+=qs; else r3+=qs;

            r0 += __shfl_xor_sync(~0u, r0, 16);
            r1 += __shfl_xor_sync(~0u, r1, 16);
            r2 += __shfl_xor_sync(~0u, r2, 16);
            r3 += __shfl_xor_sync(~0u, r3, 16);
            r0 += __shfl_xor_sync(~0u, r0, 8);
            r1 += __shfl_xor_sync(~0u, r1, 8);
            r2 += __shfl_xor_sync(~0u, r2, 8);
            r3 += __shfl_xor_sync(~0u, r3, 8);
            float v = (h==0)?r0:(h==1)?r1:(h==2)?r2:r3;
            v += __shfl_xor_sync(~0u, v, 4);
            v += __shfl_xor_sync(~0u, v, 2);
            v += __shfl_xor_sync(~0u, v, 1);
            if ((lane & 7) == 0) outp[(size_t)h * NN * NN] = v + myb;
        }
    }
}

// ---------------- fast exp (no MUFU) ----------------
__device__ __forceinline__ float fexp(float x) {
    x = fmaxf(x, -87.0f);
    float y = x * 1.4426950408889634f;
    float f = floorf(y);
    float r = y - f;
    float p = 1.5403530e-4f;
    p = fmaf(p, r, 1.3333558e-3f);
    p = fmaf(p, r, 9.6181291e-3f);
    p = fmaf(p, r, 5.5504109e-2f);
    p = fmaf(p, r, 2.4022651e-1f);
    p = fmaf(p, r, 6.9314718e-1f);
    p = fmaf(p, r, 1.0f);
    return __int_as_float(__float_as_int(p) + (((int)f) << 23));
}

// ---------------- K3: fused softmax + attn@v ----------------
__global__ __launch_bounds__(256) void k_av()
{
    int b = blockIdx.z, h = blockIdx.y, i0 = blockIdx.x * 8;
    int tid = threadIdx.x, w = tid >> 5, lane = tid & 31;

    __shared__ __align__(16) float sP[8][512];
    __shared__ __align__(16) float sRed[8][8][64];
    __shared__ float sInv[8];

    {
        const float* arow = g_attn + (((size_t)(b*NH+h))*NN + (i0+w))*NN;
        float4 vv[4];
        float mx = -3.4e38f;
        #pragma unroll
        for (int t = 0; t < 4; t++) {
            vv[t] = ((const float4*)arow)[lane + 32*t];
            mx = fmaxf(mx, fmaxf(fmaxf(vv[t].x,vv[t].y), fmaxf(vv[t].z,vv[t].w)));
        }
        #pragma unroll
        for (int o = 16; o; o >>= 1) mx = fmaxf(mx, __shfl_xor_sync(~0u, mx, o));
        float s = 0.f;
        #pragma unroll
        for (int t = 0; t < 4; t++) {
            vv[t].x = fexp(vv[t].x - mx); vv[t].y = fexp(vv[t].y - mx);
            vv[t].z = fexp(vv[t].z - mx); vv[t].w = fexp(vv[t].w - mx);
            s += vv[t].x + vv[t].y + vv[t].z + vv[t].w;
            *(float4*)&sP[w][lane*4 + t*128] = vv[t];
        }
        #pragma unroll
        for (int o = 16; o; o >>= 1) s += __shfl_xor_sync(~0u, s, o);
        if (lane == 0) sInv[w] = 1.0f / s;
    }
    __syncthreads();

    float2 acc[8] = {};
    const float2* vp = (const float2*)&g_v[(b*NN + w*64)*256 + h*64 + lane*2];
    #pragma unroll 4
    for (int jj = 0; jj < 64; jj += 2) {
        float2 v0 = vp[(size_t)jj * 128];
        float2 v1 = vp[(size_t)(jj+1) * 128];
        #pragma unroll
        for (int i = 0; i < 8; i++) {
            float2 pp = *(const float2*)&sP[i][w*64 + jj];
            acc[i].x = fmaf(pp.x, v0.x, acc[i].x);
            acc[i].y = fmaf(pp.x, v0.y, acc[i].y);
            acc[i].x = fmaf(pp.y, v1.x, acc[i].x);
            acc[i].y = fmaf(pp.y, v1.y, acc[i].y);
        }
    }
    #pragma unroll
    for (int i = 0; i < 8; i++)
        *(float2*)&sRed[w][i][lane*2] = acc[i];
    __syncthreads();

    int i = tid >> 5, d = (tid * 2) & 63;
    float sx = 0.f, sy = 0.f;
    #pragma unroll
    for (int ww = 0; ww < 8; ww++) {
        float2 t = *(const float2*)&sRed[ww][i][d];
        sx += t.x; sy += t.y;
    }
    float inv = sInv[i];
    *(float2*)&g_ctx[(b*NN + i0 + i)*256 + h*64 + d] = make_float2(sx*inv, sy*inv);
}

__global__ __launch_bounds__(256) void k_out(
    const float* __restrict__ Wo, const float* __restrict__ bo,
    float* __restrict__ out)
{
    gemm64(g_ctx, Wo, bo, out, blockIdx.y * 64, blockIdx.x * 64);
}

// ---- host: Chebyshev fit of S(m) = -m*erfc(m/sqrt2), m in [0,6], deg 9 ----
static GCoef fit_gelu_poly() {
    const int DEG = 9, M = 64;
    double cc[DEG+1], fv[M];
    for (int j = 0; j < M; j++) {
        double xx = cos(M_PI * (j + 0.5) / M);
        double m = 3.0 * (xx + 1.0);
        fv[j] = -m * erfc(m * 0.7071067811865476);
    }
    for (int k = 0; k <= DEG; k++) {
        double s = 0;
        for (int j = 0; j < M; j++) s += fv[j] * cos(k * M_PI * (j + 0.5) / M);
        cc[k] = s * ((k == 0 ? 1.0 : 2.0) / M);
    }
    double mono[DEG+1] = {0}, Tm2[DEG+1] = {0}, Tm1[DEG+1] = {0}, Tk[DEG+1];
    Tm2[0] = 1.0; Tm1[1] = 1.0;
    mono[0] += cc[0];
    mono[1] += cc[1];
    for (int k = 2; k <= DEG; k++) {
        for (int i = 0; i <= DEG; i++) Tk[i] = -Tm2[i] + 2.0 * (i > 0 ? Tm1[i-1] : 0.0);
        for (int i = 0; i <= DEG; i++) mono[i] += cc[k] * Tk[i];
        for (int i = 0; i <= DEG; i++) { Tm2[i] = Tm1[i]; Tm1[i] = Tk[i]; }
    }
    GCoef g;
    for (int i = 0; i <= DEG; i++) g.c[i] = (float)mono[i];
    return g;
}

extern "C" void kernel_launch(void* const* d_in, const int* in_sizes, int n_in,
                              void* d_out, int out_size)
{
    const float* x   = (const float*)d_in[0];
    const int*   adj = (const int*)  d_in[1];
    const float* Wq  = (const float*)d_in[2];
    const float* bq  = (const float*)d_in[3];
    const float* Wk  = (const float*)d_in[4];
    const float* bk  = (const float*)d_in[5];
    const float* Wv  = (const float*)d_in[6];
    const float* bv  = (const float*)d_in[7];
    const float* Wo  = (const float*)d_in[8];
    const float* bo  = (const float*)d_in[9];
    const float* Wp1 = (const float*)d_in[10];
    const float* bp1 = (const float*)d_in[11];
    const float* Wp2 = (const float*)d_in[12];
    const float* bp2 = (const float*)d_in[13];
    float* out = (float*)d_out;

    GCoef co = fit_gelu_poly();

    dim3 g1(20, 16);
    k_proj<<<g1, 256>>>(x, Wq, bq, Wk, bk, Wv, bv, Wp1, bp1);

    dim3 g2(4, 64, 2);
    k_scores<<<g2, 256>>>(adj, Wp2, bp2, co);

    dim3 g4(64, 4, 2);
    k_av<<<g4, 256>>>();

    dim3 g5(4, 16);
    k_out<<<g5, 256>>>(Wo, bo, out);
}

// round 9
// speedup vs baseline: 1.3895x; 1.3895x over previous
#include <cuda_runtime.h>
#include <math.h>

typedef unsigned long long u64;
typedef unsigned int u32;
#define NN 512
#define NH 4
#define MR (2*NN)

__device__ float g_q[MR*256];
__device__ float g_k[MR*256];
__device__ float g_v[MR*256];
__device__ float g_a[MR*256];
__device__ float g_b[MR*256];
__device__ __align__(16) float g_attn[(size_t)2*NH*NN*NN];  // [b][h][i][j]
__device__ float g_ctx[MR*256];

struct GCoef { float c[10]; };

__device__ __forceinline__ u64 pk(float lo, float hi) {
    u64 r; asm("mov.b64 %0,{%1,%2};" : "=l"(r) : "f"(lo), "f"(hi)); return r;
}
__device__ __forceinline__ void upk(u64 v, float& lo, float& hi) {
    asm("mov.b64 {%0,%1},%2;" : "=f"(lo), "=f"(hi) : "l"(v));
}
__device__ __forceinline__ u64 f2add(u64 a, u64 b) {
    u64 d; asm("add.rn.f32x2 %0,%1,%2;" : "=l"(d) : "l"(a), "l"(b)); return d;
}
__device__ __forceinline__ u64 f2fma(u64 a, u64 b, u64 c) {
    u64 d; asm("fma.rn.f32x2 %0,%1,%2,%3;" : "=l"(d) : "l"(a), "l"(b), "l"(c)); return d;
}
__device__ __forceinline__ void cpa16(u32 dst, const void* src) {
    asm volatile("cp.async.ca.shared.global [%0], [%1], 16;" :: "r"(dst), "l"(src));
}

// ---- 64x64 GEMM, K=256, 256 thr, 4x4/thread, FMA2, reg-double-buffered ----
__device__ __forceinline__ void gemm64(
    const float* __restrict__ A, const float* __restrict__ W,
    const float* __restrict__ bias, float* __restrict__ C,
    int m0, int n0)
{
    __shared__ __align__(16) float As[2][16][68];
    __shared__ __align__(16) float Ws[2][16][68];
    int tid = threadIdx.x, tx = tid & 15, ty = tid >> 4;
    u64 acc[4][2] = {};

    int ar = tid >> 2, ac = (tid & 3) * 4;
    int wk = tid >> 4, wn = (tid & 15) * 4;

    float4 pA = *(const float4*)&A[(m0 + ar) * 256 + ac];
    float4 pW = *(const float4*)&W[wk * 256 + n0 + wn];

    int buf = 0;
    for (int t = 0; t < 16; t++) {
        As[buf][ac+0][ar] = pA.x; As[buf][ac+1][ar] = pA.y;
        As[buf][ac+2][ar] = pA.z; As[buf][ac+3][ar] = pA.w;
        *(float4*)&Ws[buf][wk][wn] = pW;
        __syncthreads();
        if (t < 15) {
            int k0 = (t + 1) * 16;
            pA = *(const float4*)&A[(m0 + ar) * 256 + k0 + ac];
            pW = *(const float4*)&W[(k0 + wk) * 256 + n0 + wn];
        }
        #pragma unroll
        for (int kk = 0; kk < 16; kk++) {
            float4 ra = *(const float4*)&As[buf][kk][ty * 4];
            ulonglong2 wv = *(const ulonglong2*)&Ws[buf][kk][tx * 4];
            u64 r0 = pk(ra.x, ra.x), r1 = pk(ra.y, ra.y);
            u64 r2 = pk(ra.z, ra.z), r3 = pk(ra.w, ra.w);
            acc[0][0] = f2fma(r0, wv.x, acc[0][0]);
            acc[0][1] = f2fma(r0, wv.y, acc[0][1]);
            acc[1][0] = f2fma(r1, wv.x, acc[1][0]);
            acc[1][1] = f2fma(r1, wv.y, acc[1][1]);
            acc[2][0] = f2fma(r2, wv.x, acc[2][0]);
            acc[2][1] = f2fma(r2, wv.y, acc[2][1]);
            acc[3][0] = f2fma(r3, wv.x, acc[3][0]);
            acc[3][1] = f2fma(r3, wv.y, acc[3][1]);
        }
        buf ^= 1;
    }
    int n = n0 + tx * 4;
    float b0 = 0.f, b1 = 0.f, b2 = 0.f, b3 = 0.f;
    if (bias) { b0 = bias[n]; b1 = bias[n+1]; b2 = bias[n+2]; b3 = bias[n+3]; }
    #pragma unroll
    for (int i = 0; i < 4; i++) {
        float o0,o1,o2,o3;
        upk(acc[i][0], o0, o1); upk(acc[i][1], o2, o3);
        *(float4*)&C[(m0 + ty*4 + i) * 256 + n] =
            make_float4(o0 + b0, o1 + b1, o2 + b2, o3 + b3);
    }
}

__global__ __launch_bounds__(256) void k_proj(
    const float* __restrict__ x,
    const float* __restrict__ Wq, const float* __restrict__ bq,
    const float* __restrict__ Wk, const float* __restrict__ bk,
    const float* __restrict__ Wv, const float* __restrict__ bv,
    const float* __restrict__ Wp1, const float* __restrict__ bp1)
{
    int bn = blockIdx.x;
    int seg = bn >> 2, n0 = (bn & 3) * 64;
    const float* W; const float* bias; float* C;
    switch (seg) {
        case 0: W = Wq; bias = bq; C = g_q; break;
        case 1: W = Wk; bias = bk; C = g_k; break;
        case 2: W = Wv; bias = bv; C = g_v; break;
        case 3: W = Wp1; bias = nullptr; C = g_a; break;
        default: W = Wp1 + 256*256; bias = bp1; C = g_b; break;  // bp1 folded
    }
    gemm64(x, W, bias, C, blockIdx.y * 64, n0);
}

// ------- K2: fused pair scores (R7 base + cp.async double-buffered tiles) -------
__global__ __launch_bounds__(256, 2) void k_scores(
    const int* __restrict__ adj, const float* __restrict__ Wp2,
    const float* __restrict__ bp2, GCoef co)
{
    int b = blockIdx.z, i0 = blockIdx.y * 8, j0base = blockIdx.x * 128;
    int tid = threadIdx.x, lane = tid & 31, w = tid >> 5;
    int h = lane >> 3;

    __shared__ __align__(16) float sA[8][256], sQ[8][256];
    __shared__ __align__(16) float sB[2][8][256], sK[2][8][256];
    __shared__ int sM[8][128];

    u32 sBu = (u32)__cvta_generic_to_shared(sB);
    u32 sKu = (u32)__cvta_generic_to_shared(sK);
    const char* gB0 = (const char*)(g_b + (b * NN + j0base) * 256);
    const char* gK0 = (const char*)(g_k + (b * NN + j0base) * 256);
    int cpo = tid * 16;

    auto PREF = [&](int tile, int buf) {
        cpa16(sBu + buf*8192 + cpo,        gB0 + tile*8192 + cpo);
        cpa16(sBu + buf*8192 + cpo + 4096, gB0 + tile*8192 + cpo + 4096);
        cpa16(sKu + buf*8192 + cpo,        gK0 + tile*8192 + cpo);
        cpa16(sKu + buf*8192 + cpo + 4096, gK0 + tile*8192 + cpo + 4096);
        asm volatile("cp.async.commit_group;");
    };
    PREF(0, 0); PREF(1, 1);

    u64 C[10];
    #pragma unroll
    for (int kk = 0; kk < 10; kk++) C[kk] = pk(co.c[kk], co.c[kk]);
    const u64 K3 = pk(1.0f/3.0f, 1.0f/3.0f);
    const u64 KM1 = pk(-1.0f, -1.0f);
    const u64 KABS = 0x7FFFFFFF7FFFFFFFull;

    u64 w2[4][4];
    {
        int cb = lane * 8;
        #pragma unroll
        for (int p = 0; p < 4; p++) {
            float4 wa = *(const float4*)&Wp2[(cb + 2*p) * 4];
            float4 wb = *(const float4*)&Wp2[(cb + 2*p + 1) * 4];
            w2[p][0] = pk(0.5f*wa.x, 0.5f*wb.x);
            w2[p][1] = pk(0.5f*wa.y, 0.5f*wb.y);
            w2[p][2] = pk(0.5f*wa.z, 0.5f*wb.z);
            w2[p][3] = pk(0.5f*wa.w, 0.5f*wb.w);
        }
    }
    float myb = bp2[h];

    const float* aptr = g_a + (b * NN + i0) * 256;
    const float* qptr = g_q + (b * NN + i0) * 256;
    #pragma unroll
    for (int t = 0; t < 2; t++) {
        int idx = tid + t * 256;
        ((float4*)sA)[idx] = ((const float4*)aptr)[idx];
        ((float4*)sQ)[idx] = ((const float4*)qptr)[idx];
    }
    #pragma unroll
    for (int t = 0; t < 4; t++) {
        int idx = tid + t * 256;
        sM[idx >> 7][idx & 127] = adj[(i0 + (idx >> 7)) * NN + j0base + (idx & 127)];
    }

    for (int jc = 0; jc < 16; jc++) {
        if (jc < 15) asm volatile("cp.async.wait_group 1;");
        else         asm volatile("cp.async.wait_group 0;");
        __syncthreads();
        int buf = jc & 1;
        int j = j0base + jc * 8 + w;

        u64 bbp[4], kvp[4];
        {
            ulonglong2 x0 = *(const ulonglong2*)&sB[buf][w][lane*8];
            ulonglong2 x1 = *(const ulonglong2*)&sB[buf][w][lane*8+4];
            bbp[0]=x0.x; bbp[1]=x0.y; bbp[2]=x1.x; bbp[3]=x1.y;
            ulonglong2 y0 = *(const ulonglong2*)&sK[buf][w][lane*8];
            ulonglong2 y1 = *(const ulonglong2*)&sK[buf][w][lane*8+4];
            kvp[0]=y0.x; kvp[1]=y0.y; kvp[2]=y1.x; kvp[3]=y1.y;
        }

        #pragma unroll
        for (int il = 0; il < 8; il++) {
            int mval = sM[il][jc * 8 + w];
            int i = i0 + il;
            float* outp = &g_attn[((size_t)(b * NH) * NN + i) * NN + j];
            if (mval == 0) {
                if ((lane & 7) == 0) outp[(size_t)h * NN * NN] = -1e9f;
                continue;
            }
            u64 aA[4], qA[4];
            {
                ulonglong2 x0 = *(const ulonglong2*)&sA[il][lane*8];
                ulonglong2 x1 = *(const ulonglong2*)&sA[il][lane*8+4];
                aA[0]=x0.x; aA[1]=x0.y; aA[2]=x1.x; aA[3]=x1.y;
                ulonglong2 y0 = *(const ulonglong2*)&sQ[il][lane*8];
                ulonglong2 y1 = *(const ulonglong2*)&sQ[il][lane*8+4];
                qA[0]=y0.x; qA[1]=y0.y; qA[2]=y1.x; qA[3]=y1.y;
            }
            u64 aw0=0, aw1=0, aw2=0, aw3=0, qk=0;
            #pragma unroll
            for (int p = 0; p < 4; p++) {
                u64 t = f2add(aA[p], bbp[p]);
                u64 m = t & KABS;
                u64 wv = f2fma(m, K3, KM1);
                u64 S = C[9];
                #pragma unroll
                for (int kk = 8; kk >= 0; kk--) S = f2fma(S, wv, C[kk]);
                u64 G = f2add(f2add(t, m), S);   // 2*gelu
                aw0 = f2fma(G, w2[p][0], aw0);
                aw1 = f2fma(G, w2[p][1], aw1);
                aw2 = f2fma(G, w2[p][2], aw2);
                aw3 = f2fma(G, w2[p][3], aw3);
                qk  = f2fma(qA[p], kvp[p], qk);
            }
            float r0,r1,r2,r3,x0,x1,qx,qy;
            upk(aw0,r0,x0); r0+=x0;
            upk(aw1,r1,x1); r1+=x1;
            upk(aw2,r2,x0); r2+=x0;
            upk(aw3,r3,x1); r3+=x1;
            upk(qk,qx,qy);
            float qs = (qx+qy)*0.125f;
            if (h==0) r0+=qs; else if (h==1) r1+=qs; else if (h==2) r2+=qs; else r3+=qs;

            r0 += __shfl_xor_sync(~0u, r0, 16);
            r1 += __shfl_xor_sync(~0u, r1, 16);
            r2 += __shfl_xor_sync(~0u, r2, 16);
            r3 += __shfl_xor_sync(~0u, r3, 16);
            r0 += __shfl_xor_sync(~0u, r0, 8);
            r1 += __shfl_xor_sync(~0u, r1, 8);
            r2 += __shfl_xor_sync(~0u, r2, 8);
            r3 += __shfl_xor_sync(~0u, r3, 8);
            float v = (h==0)?r0:(h==1)?r1:(h==2)?r2:r3;
            v += __shfl_xor_sync(~0u, v, 4);
            v += __shfl_xor_sync(~0u, v, 2);
            v += __shfl_xor_sync(~0u, v, 1);
            if ((lane & 7) == 0) outp[(size_t)h * NN * NN] = v + myb;
        }
        __syncthreads();
        if (jc + 2 < 16) PREF(jc + 2, buf);
    }
}

// ---------------- fast exp (no MUFU) ----------------
__device__ __forceinline__ float fexp(float x) {
    x = fmaxf(x, -87.0f);
    float y = x * 1.4426950408889634f;
    float f = floorf(y);
    float r = y - f;
    float p = 1.5403530e-4f;
    p = fmaf(p, r, 1.3333558e-3f);
    p = fmaf(p, r, 9.6181291e-3f);
    p = fmaf(p, r, 5.5504109e-2f);
    p = fmaf(p, r, 2.4022651e-1f);
    p = fmaf(p, r, 6.9314718e-1f);
    p = fmaf(p, r, 1.0f);
    return __int_as_float(__float_as_int(p) + (((int)f) << 23));
}

// ---------------- K3: fused softmax + attn@v (R7/R4-best) ----------------
__global__ __launch_bounds__(256) void k_av()
{
    int b = blockIdx.z, h = blockIdx.y, i0 = blockIdx.x * 8;
    int tid = threadIdx.x, w = tid >> 5, lane = tid & 31;

    __shared__ __align__(16) float sP[8][512];
    __shared__ __align__(16) float sRed[8][8][64];
    __shared__ float sInv[8];

    {
        const float* arow = g_attn + (((size_t)(b*NH+h))*NN + (i0+w))*NN;
        float4 vv[4];
        float mx = -3.4e38f;
        #pragma unroll
        for (int t = 0; t < 4; t++) {
            vv[t] = ((const float4*)arow)[lane + 32*t];
            mx = fmaxf(mx, fmaxf(fmaxf(vv[t].x,vv[t].y), fmaxf(vv[t].z,vv[t].w)));
        }
        #pragma unroll
        for (int o = 16; o; o >>= 1) mx = fmaxf(mx, __shfl_xor_sync(~0u, mx, o));
        float s = 0.f;
        #pragma unroll
        for (int t = 0; t < 4; t++) {
            vv[t].x = fexp(vv[t].x - mx); vv[t].y = fexp(vv[t].y - mx);
            vv[t].z = fexp(vv[t].z - mx); vv[t].w = fexp(vv[t].w - mx);
            s += vv[t].x + vv[t].y + vv[t].z + vv[t].w;
            *(float4*)&sP[w][lane*4 + t*128] = vv[t];
        }
        #pragma unroll
        for (int o = 16; o; o >>= 1) s += __shfl_xor_sync(~0u, s, o);
        if (lane == 0) sInv[w] = 1.0f / s;
    }
    __syncthreads();

    float2 acc[8] = {};
    const float2* vp = (const float2*)&g_v[(b*NN + w*64)*256 + h*64 + lane*2];
    #pragma unroll 4
    for (int jj = 0; jj < 64; jj += 2) {
        float2 v0 = vp[(size_t)jj * 128];
        float2 v1 = vp[(size_t)(jj+1) * 128];
        #pragma unroll
        for (int i = 0; i < 8; i++) {
            float2 pp = *(const float2*)&sP[i][w*64 + jj];
            acc[i].x = fmaf(pp.x, v0.x, acc[i].x);
            acc[i].y = fmaf(pp.x, v0.y, acc[i].y);
            acc[i].x = fmaf(pp.y, v1.x, acc[i].x);
            acc[i].y = fmaf(pp.y, v1.y, acc[i].y);
        }
    }
    #pragma unroll
    for (int i = 0; i < 8; i++)
        *(float2*)&sRed[w][i][lane*2] = acc[i];
    __syncthreads();

    int i = tid >> 5, d = (tid * 2) & 63;
    float sx = 0.f, sy = 0.f;
    #pragma unroll
    for (int ww = 0; ww < 8; ww++) {
        float2 t = *(const float2*)&sRed[ww][i][d];
        sx += t.x; sy += t.y;
    }
    float inv = sInv[i];
    *(float2*)&g_ctx[(b*NN + i0 + i)*256 + h*64 + d] = make_float2(sx*inv, sy*inv);
}

__global__ __launch_bounds__(256) void k_out(
    const float* __restrict__ Wo, const float* __restrict__ bo,
    float* __restrict__ out)
{
    gemm64(g_ctx, Wo, bo, out, blockIdx.y * 64, blockIdx.x * 64);
}

// ---- host: Chebyshev fit of S(m) = -m*erfc(m/sqrt2), m in [0,6], deg 9 ----
static GCoef fit_gelu_poly() {
    const int DEG = 9, M = 64;
    double cc[DEG+1], fv[M];
    for (int j = 0; j < M; j++) {
        double xx = cos(M_PI * (j + 0.5) / M);
        double m = 3.0 * (xx + 1.0);
        fv[j] = -m * erfc(m * 0.7071067811865476);
    }
    for (int k = 0; k <= DEG; k++) {
        double s = 0;
        for (int j = 0; j < M; j++) s += fv[j] * cos(k * M_PI * (j + 0.5) / M);
        cc[k] = s * ((k == 0 ? 1.0 : 2.0) / M);
    }
    double mono[DEG+1] = {0}, Tm2[DEG+1] = {0}, Tm1[DEG+1] = {0}, Tk[DEG+1];
    Tm2[0] = 1.0; Tm1[1] = 1.0;
    mono[0] += cc[0];
    mono[1] += cc[1];
    for (int k = 2; k <= DEG; k++) {
        for (int i = 0; i <= DEG; i++) Tk[i] = -Tm2[i] + 2.0 * (i > 0 ? Tm1[i-1] : 0.0);
        for (int i = 0; i <= DEG; i++) mono[i] += cc[k] * Tk[i];
        for (int i = 0; i <= DEG; i++) { Tm2[i] = Tm1[i]; Tm1[i] = Tk[i]; }
    }
    GCoef g;
    for (int i = 0; i <= DEG; i++) g.c[i] = (float)mono[i];
    return g;
}

extern "C" void kernel_launch(void* const* d_in, const int* in_sizes, int n_in,
                              void* d_out, int out_size)
{
    const float* x   = (const float*)d_in[0];
    const int*   adj = (const int*)  d_in[1];
    const float* Wq  = (const float*)d_in[2];
    const float* bq  = (const float*)d_in[3];
    const float* Wk  = (const float*)d_in[4];
    const float* bk  = (const float*)d_in[5];
    const float* Wv  = (const float*)d_in[6];
    const float* bv  = (const float*)d_in[7];
    const float* Wo  = (const float*)d_in[8];
    const float* bo  = (const float*)d_in[9];
    const float* Wp1 = (const float*)d_in[10];
    const float* bp1 = (const float*)d_in[11];
    const float* Wp2 = (const float*)d_in[12];
    const float* bp2 = (const float*)d_in[13];
    float* out = (float*)d_out;

    GCoef co = fit_gelu_poly();

    dim3 g1(20, 16);
    k_proj<<<g1, 256>>>(x, Wq, bq, Wk, bk, Wv, bv, Wp1, bp1);

    dim3 g2(4, 64, 2);
    k_scores<<<g2, 256>>>(adj, Wp2, bp2, co);

    dim3 g4(64, 4, 2);
    k_av<<<g4, 256>>>();

    dim3 g5(4, 16);
    k_out<<<g5, 256>>>(Wo, bo, out);
}

// round 10
// speedup vs baseline: 1.5002x; 1.0796x over previous
#include <cuda_runtime.h>
#include <math.h>

typedef unsigned long long u64;
typedef unsigned int u32;
#define NN 512
#define NH 4
#define MR (2*NN)

__device__ float g_q[MR*256];
__device__ float g_k[MR*256];
__device__ float g_v[MR*256];
__device__ float g_a[MR*256];
__device__ float g_b[MR*256];
__device__ __align__(16) float g_attn[(size_t)2*NH*NN*NN];  // [b][h][i][j]
__device__ float g_ctx[MR*256];

struct GCoef { float c[10]; };

__device__ __forceinline__ u64 pk(float lo, float hi) {
    u64 r; asm("mov.b64 %0,{%1,%2};" : "=l"(r) : "f"(lo), "f"(hi)); return r;
}
__device__ __forceinline__ void upk(u64 v, float& lo, float& hi) {
    asm("mov.b64 {%0,%1},%2;" : "=f"(lo), "=f"(hi) : "l"(v));
}
__device__ __forceinline__ u64 f2add(u64 a, u64 b) {
    u64 d; asm("add.rn.f32x2 %0,%1,%2;" : "=l"(d) : "l"(a), "l"(b)); return d;
}
__device__ __forceinline__ u64 f2fma(u64 a, u64 b, u64 c) {
    u64 d; asm("fma.rn.f32x2 %0,%1,%2,%3;" : "=l"(d) : "l"(a), "l"(b), "l"(c)); return d;
}
__device__ __forceinline__ void cpa16(u32 dst, const void* src) {
    asm volatile("cp.async.ca.shared.global [%0], [%1], 16;" :: "r"(dst), "l"(src));
}

// ---- 64x64 GEMM, K=256, 256 thr, 4x4/thread, FMA2, reg-double-buffered ----
__device__ __forceinline__ void gemm64(
    const float* __restrict__ A, const float* __restrict__ W,
    const float* __restrict__ bias, float* __restrict__ C,
    int m0, int n0)
{
    __shared__ __align__(16) float As[2][16][68];
    __shared__ __align__(16) float Ws[2][16][68];
    int tid = threadIdx.x, tx = tid & 15, ty = tid >> 4;
    u64 acc[4][2] = {};

    int ar = tid >> 2, ac = (tid & 3) * 4;
    int wk = tid >> 4, wn = (tid & 15) * 4;

    float4 pA = *(const float4*)&A[(m0 + ar) * 256 + ac];
    float4 pW = *(const float4*)&W[wk * 256 + n0 + wn];

    int buf = 0;
    for (int t = 0; t < 16; t++) {
        As[buf][ac+0][ar] = pA.x; As[buf][ac+1][ar] = pA.y;
        As[buf][ac+2][ar] = pA.z; As[buf][ac+3][ar] = pA.w;
        *(float4*)&Ws[buf][wk][wn] = pW;
        __syncthreads();
        if (t < 15) {
            int k0 = (t + 1) * 16;
            pA = *(const float4*)&A[(m0 + ar) * 256 + k0 + ac];
            pW = *(const float4*)&W[(k0 + wk) * 256 + n0 + wn];
        }
        #pragma unroll
        for (int kk = 0; kk < 16; kk++) {
            float4 ra = *(const float4*)&As[buf][kk][ty * 4];
            ulonglong2 wv = *(const ulonglong2*)&Ws[buf][kk][tx * 4];
            u64 r0 = pk(ra.x, ra.x), r1 = pk(ra.y, ra.y);
            u64 r2 = pk(ra.z, ra.z), r3 = pk(ra.w, ra.w);
            acc[0][0] = f2fma(r0, wv.x, acc[0][0]);
            acc[0][1] = f2fma(r0, wv.y, acc[0][1]);
            acc[1][0] = f2fma(r1, wv.x, acc[1][0]);
            acc[1][1] = f2fma(r1, wv.y, acc[1][1]);
            acc[2][0] = f2fma(r2, wv.x, acc[2][0]);
            acc[2][1] = f2fma(r2, wv.y, acc[2][1]);
            acc[3][0] = f2fma(r3, wv.x, acc[3][0]);
            acc[3][1] = f2fma(r3, wv.y, acc[3][1]);
        }
        buf ^= 1;
    }
    int n = n0 + tx * 4;
    float b0 = 0.f, b1 = 0.f, b2 = 0.f, b3 = 0.f;
    if (bias) { b0 = bias[n]; b1 = bias[n+1]; b2 = bias[n+2]; b3 = bias[n+3]; }
    #pragma unroll
    for (int i = 0; i < 4; i++) {
        float o0,o1,o2,o3;
        upk(acc[i][0], o0, o1); upk(acc[i][1], o2, o3);
        *(float4*)&C[(m0 + ty*4 + i) * 256 + n] =
            make_float4(o0 + b0, o1 + b1, o2 + b2, o3 + b3);
    }
}

__global__ __launch_bounds__(256) void k_proj(
    const float* __restrict__ x,
    const float* __restrict__ Wq, const float* __restrict__ bq,
    const float* __restrict__ Wk, const float* __restrict__ bk,
    const float* __restrict__ Wv, const float* __restrict__ bv,
    const float* __restrict__ Wp1, const float* __restrict__ bp1)
{
    int bn = blockIdx.x;
    int seg = bn >> 2, n0 = (bn & 3) * 64;
    const float* W; const float* bias; float* C;
    switch (seg) {
        case 0: W = Wq; bias = bq; C = g_q; break;
        case 1: W = Wk; bias = bk; C = g_k; break;
        case 2: W = Wv; bias = bv; C = g_v; break;
        case 3: W = Wp1; bias = nullptr; C = g_a; break;
        default: W = Wp1 + 256*256; bias = bp1; C = g_b; break;  // bp1 folded
    }
    gemm64(x, W, bias, C, blockIdx.y * 64, n0);
}

// ------- K2: fused pair scores (cp.async tiles + 6-shfl epilogue) -------
__global__ __launch_bounds__(256, 2) void k_scores(
    const int* __restrict__ adj, const float* __restrict__ Wp2,
    const float* __restrict__ bp2, GCoef co)
{
    int b = blockIdx.z, i0 = blockIdx.y * 8, j0base = blockIdx.x * 128;
    int tid = threadIdx.x, lane = tid & 31, w = tid >> 5;
    int h = lane >> 3;

    __shared__ __align__(16) float sA[8][256], sQ[8][256];
    __shared__ __align__(16) float sB[2][8][256], sK[2][8][256];
    __shared__ int sM[8][128];

    u32 sBu = (u32)__cvta_generic_to_shared(sB);
    u32 sKu = (u32)__cvta_generic_to_shared(sK);
    const char* gB0 = (const char*)(g_b + (b * NN + j0base) * 256);
    const char* gK0 = (const char*)(g_k + (b * NN + j0base) * 256);
    int cpo = tid * 16;

    auto PREF = [&](int tile, int buf) {
        cpa16(sBu + buf*8192 + cpo,        gB0 + tile*8192 + cpo);
        cpa16(sBu + buf*8192 + cpo + 4096, gB0 + tile*8192 + cpo + 4096);
        cpa16(sKu + buf*8192 + cpo,        gK0 + tile*8192 + cpo);
        cpa16(sKu + buf*8192 + cpo + 4096, gK0 + tile*8192 + cpo + 4096);
        asm volatile("cp.async.commit_group;");
    };
    PREF(0, 0); PREF(1, 1);

    u64 C[10];
    #pragma unroll
    for (int kk = 0; kk < 10; kk++) C[kk] = pk(co.c[kk], co.c[kk]);
    const u64 K3 = pk(1.0f/3.0f, 1.0f/3.0f);
    const u64 KM1 = pk(-1.0f, -1.0f);
    const u64 KABS = 0x7FFFFFFF7FFFFFFFull;

    u64 w2[4][4];
    {
        int cb = lane * 8;
        #pragma unroll
        for (int p = 0; p < 4; p++) {
            float4 wa = *(const float4*)&Wp2[(cb + 2*p) * 4];
            float4 wb = *(const float4*)&Wp2[(cb + 2*p + 1) * 4];
            w2[p][0] = pk(0.5f*wa.x, 0.5f*wb.x);
            w2[p][1] = pk(0.5f*wa.y, 0.5f*wb.y);
            w2[p][2] = pk(0.5f*wa.z, 0.5f*wb.z);
            w2[p][3] = pk(0.5f*wa.w, 0.5f*wb.w);
        }
    }
    float myb = bp2[h];
    bool up = lane >= 16;
    bool g1sel = (lane & 8) != 0;

    const float* aptr = g_a + (b * NN + i0) * 256;
    const float* qptr = g_q + (b * NN + i0) * 256;
    #pragma unroll
    for (int t = 0; t < 2; t++) {
        int idx = tid + t * 256;
        ((float4*)sA)[idx] = ((const float4*)aptr)[idx];
        ((float4*)sQ)[idx] = ((const float4*)qptr)[idx];
    }
    #pragma unroll
    for (int t = 0; t < 4; t++) {
        int idx = tid + t * 256;
        sM[idx >> 7][idx & 127] = adj[(i0 + (idx >> 7)) * NN + j0base + (idx & 127)];
    }

    for (int jc = 0; jc < 16; jc++) {
        if (jc < 15) asm volatile("cp.async.wait_group 1;");
        else         asm volatile("cp.async.wait_group 0;");
        __syncthreads();
        int buf = jc & 1;
        int j = j0base + jc * 8 + w;

        u64 bbp[4], kvp[4];
        {
            ulonglong2 x0 = *(const ulonglong2*)&sB[buf][w][lane*8];
            ulonglong2 x1 = *(const ulonglong2*)&sB[buf][w][lane*8+4];
            bbp[0]=x0.x; bbp[1]=x0.y; bbp[2]=x1.x; bbp[3]=x1.y;
            ulonglong2 y0 = *(const ulonglong2*)&sK[buf][w][lane*8];
            ulonglong2 y1 = *(const ulonglong2*)&sK[buf][w][lane*8+4];
            kvp[0]=y0.x; kvp[1]=y0.y; kvp[2]=y1.x; kvp[3]=y1.y;
        }

        #pragma unroll
        for (int il = 0; il < 8; il++) {
            int mval = sM[il][jc * 8 + w];
            int i = i0 + il;
            float* outp = &g_attn[((size_t)(b * NH) * NN + i) * NN + j];
            if (mval == 0) {
                if ((lane & 7) == 0) outp[(size_t)h * NN * NN] = -1e9f;
                continue;
            }
            u64 aA[4], qA[4];
            {
                ulonglong2 x0 = *(const ulonglong2*)&sA[il][lane*8];
                ulonglong2 x1 = *(const ulonglong2*)&sA[il][lane*8+4];
                aA[0]=x0.x; aA[1]=x0.y; aA[2]=x1.x; aA[3]=x1.y;
                ulonglong2 y0 = *(const ulonglong2*)&sQ[il][lane*8];
                ulonglong2 y1 = *(const ulonglong2*)&sQ[il][lane*8+4];
                qA[0]=y0.x; qA[1]=y0.y; qA[2]=y1.x; qA[3]=y1.y;
            }
            u64 aw0=0, aw1=0, aw2=0, aw3=0, qk=0;
            #pragma unroll
            for (int p = 0; p < 4; p++) {
                u64 t = f2add(aA[p], bbp[p]);
                u64 m = t & KABS;
                u64 wv = f2fma(m, K3, KM1);
                u64 S = C[9];
                #pragma unroll
                for (int kk = 8; kk >= 0; kk--) S = f2fma(S, wv, C[kk]);
                u64 G = f2add(f2add(t, m), S);   // 2*gelu
                aw0 = f2fma(G, w2[p][0], aw0);
                aw1 = f2fma(G, w2[p][1], aw1);
                aw2 = f2fma(G, w2[p][2], aw2);
                aw3 = f2fma(G, w2[p][3], aw3);
                qk  = f2fma(qA[p], kvp[p], qk);
            }
            float r0,r1,r2,r3,x0,x1,qx,qy;
            upk(aw0,r0,x0); r0+=x0;
            upk(aw1,r1,x1); r1+=x1;
            upk(aw2,r2,x0); r2+=x0;
            upk(aw3,r3,x1); r3+=x1;
            upk(qk,qx,qy);
            float qs = (qx+qy)*0.125f;
            if (h==0) r0+=qs; else if (h==1) r1+=qs; else if (h==2) r2+=qs; else r3+=qs;

            // 6-shfl multi-value reduction
            float s1 = up ? r0 : r2;
            float t1 = up ? r1 : r3;
            s1 = __shfl_xor_sync(~0u, s1, 16);
            t1 = __shfl_xor_sync(~0u, t1, 16);
            float ra, rb;
            if (!up) { ra = r0 + s1; rb = r1 + t1; }
            else     { ra = r2 + s1; rb = r3 + t1; }
            float u8 = g1sel ? ra : rb;
            u8 = __shfl_xor_sync(~0u, u8, 8);
            float v = g1sel ? (rb + u8) : (ra + u8);
            v += __shfl_xor_sync(~0u, v, 4);
            v += __shfl_xor_sync(~0u, v, 2);
            v += __shfl_xor_sync(~0u, v, 1);
            if ((lane & 7) == 0) outp[(size_t)h * NN * NN] = v + myb;
        }
        __syncthreads();
        if (jc + 2 < 16) PREF(jc + 2, buf);
    }
}

// ---------------- fast exp (no MUFU) ----------------
__device__ __forceinline__ float fexp(float x) {
    x = fmaxf(x, -87.0f);
    float y = x * 1.4426950408889634f;
    float f = floorf(y);
    float r = y - f;
    float p = 1.5403530e-4f;
    p = fmaf(p, r, 1.3333558e-3f);
    p = fmaf(p, r, 9.6181291e-3f);
    p = fmaf(p, r, 5.5504109e-2f);
    p = fmaf(p, r, 2.4022651e-1f);
    p = fmaf(p, r, 6.9314718e-1f);
    p = fmaf(p, r, 1.0f);
    return __int_as_float(__float_as_int(p) + (((int)f) << 23));
}

// ---------------- K3: fused softmax + attn@v (batched V loads) ----------------
__global__ __launch_bounds__(256) void k_av()
{
    int b = blockIdx.z, h = blockIdx.y, i0 = blockIdx.x * 8;
    int tid = threadIdx.x, w = tid >> 5, lane = tid & 31;

    __shared__ __align__(16) float sP[8][512];
    __shared__ __align__(16) float sRed[8][8][64];
    __shared__ float sInv[8];

    {
        const float* arow = g_attn + (((size_t)(b*NH+h))*NN + (i0+w))*NN;
        float4 vv[4];
        float mx = -3.4e38f;
        #pragma unroll
        for (int t = 0; t < 4; t++) {
            vv[t] = ((const float4*)arow)[lane + 32*t];
            mx = fmaxf(mx, fmaxf(fmaxf(vv[t].x,vv[t].y), fmaxf(vv[t].z,vv[t].w)));
        }
        #pragma unroll
        for (int o = 16; o; o >>= 1) mx = fmaxf(mx, __shfl_xor_sync(~0u, mx, o));
        float s = 0.f;
        #pragma unroll
        for (int t = 0; t < 4; t++) {
            vv[t].x = fexp(vv[t].x - mx); vv[t].y = fexp(vv[t].y - mx);
            vv[t].z = fexp(vv[t].z - mx); vv[t].w = fexp(vv[t].w - mx);
            s += vv[t].x + vv[t].y + vv[t].z + vv[t].w;
            *(float4*)&sP[w][lane*4 + t*128] = vv[t];
        }
        #pragma unroll
        for (int o = 16; o; o >>= 1) s += __shfl_xor_sync(~0u, s, o);
        if (lane == 0) sInv[w] = 1.0f / s;
    }
    __syncthreads();

    // phase B: warp w owns j in [w*64, w*64+64); lane owns d-pair; batch 8 V loads
    float2 acc[8] = {};
    const float2* vp = (const float2*)&g_v[(b*NN + w*64)*256 + h*64 + lane*2];
    #pragma unroll 2
    for (int jj = 0; jj < 64; jj += 8) {
        float2 v[8];
        #pragma unroll
        for (int u = 0; u < 8; u++) v[u] = vp[(size_t)(jj + u) * 128];
        #pragma unroll
        for (int i = 0; i < 8; i++) {
            float4 pa = *(const float4*)&sP[i][w*64 + jj];
            float4 pb = *(const float4*)&sP[i][w*64 + jj + 4];
            acc[i].x = fmaf(pa.x, v[0].x, acc[i].x); acc[i].y = fmaf(pa.x, v[0].y, acc[i].y);
            acc[i].x = fmaf(pa.y, v[1].x, acc[i].x); acc[i].y = fmaf(pa.y, v[1].y, acc[i].y);
            acc[i].x = fmaf(pa.z, v[2].x, acc[i].x); acc[i].y = fmaf(pa.z, v[2].y, acc[i].y);
            acc[i].x = fmaf(pa.w, v[3].x, acc[i].x); acc[i].y = fmaf(pa.w, v[3].y, acc[i].y);
            acc[i].x = fmaf(pb.x, v[4].x, acc[i].x); acc[i].y = fmaf(pb.x, v[4].y, acc[i].y);
            acc[i].x = fmaf(pb.y, v[5].x, acc[i].x); acc[i].y = fmaf(pb.y, v[5].y, acc[i].y);
            acc[i].x = fmaf(pb.z, v[6].x, acc[i].x); acc[i].y = fmaf(pb.z, v[6].y, acc[i].y);
            acc[i].x = fmaf(pb.w, v[7].x, acc[i].x); acc[i].y = fmaf(pb.w, v[7].y, acc[i].y);
        }
    }
    #pragma unroll
    for (int i = 0; i < 8; i++)
        *(float2*)&sRed[w][i][lane*2] = acc[i];
    __syncthreads();

    int i = tid >> 5, d = (tid * 2) & 63;
    float sx = 0.f, sy = 0.f;
    #pragma unroll
    for (int ww = 0; ww < 8; ww++) {
        float2 t = *(const float2*)&sRed[ww][i][d];
        sx += t.x; sy += t.y;
    }
    float inv = sInv[i];
    *(float2*)&g_ctx[(b*NN + i0 + i)*256 + h*64 + d] = make_float2(sx*inv, sy*inv);
}

__global__ __launch_bounds__(256) void k_out(
    const float* __restrict__ Wo, const float* __restrict__ bo,
    float* __restrict__ out)
{
    gemm64(g_ctx, Wo, bo, out, blockIdx.y * 64, blockIdx.x * 64);
}

// ---- host: Chebyshev fit of S(m) = -m*erfc(m/sqrt2), m in [0,6], deg 9 ----
static GCoef fit_gelu_poly() {
    const int DEG = 9, M = 64;
    double cc[DEG+1], fv[M];
    for (int j = 0; j < M; j++) {
        double xx = cos(M_PI * (j + 0.5) / M);
        double m = 3.0 * (xx + 1.0);
        fv[j] = -m * erfc(m * 0.7071067811865476);
    }
    for (int k = 0; k <= DEG; k++) {
        double s = 0;
        for (int j = 0; j < M; j++) s += fv[j] * cos(k * M_PI * (j + 0.5) / M);
        cc[k] = s * ((k == 0 ? 1.0 : 2.0) / M);
    }
    double mono[DEG+1] = {0}, Tm2[DEG+1] = {0}, Tm1[DEG+1] = {0}, Tk[DEG+1];
    Tm2[0] = 1.0; Tm1[1] = 1.0;
    mono[0] += cc[0];
    mono[1] += cc[1];
    for (int k = 2; k <= DEG; k++) {
        for (int i = 0; i <= DEG; i++) Tk[i] = -Tm2[i] + 2.0 * (i > 0 ? Tm1[i-1] : 0.0);
        for (int i = 0; i <= DEG; i++) mono[i] += cc[k] * Tk[i];
        for (int i = 0; i <= DEG; i++) { Tm2[i] = Tm1[i]; Tm1[i] = Tk[i]; }
    }
    GCoef g;
    for (int i = 0; i <= DEG; i++) g.c[i] = (float)mono[i];
    return g;
}

extern "C" void kernel_launch(void* const* d_in, const int* in_sizes, int n_in,
                              void* d_out, int out_size)
{
    const float* x   = (const float*)d_in[0];
    const int*   adj = (const int*)  d_in[1];
    const float* Wq  = (const float*)d_in[2];
    const float* bq  = (const float*)d_in[3];
    const float* Wk  = (const float*)d_in[4];
    const float* bk  = (const float*)d_in[5];
    const float* Wv  = (const float*)d_in[6];
    const float* bv  = (const float*)d_in[7];
    const float* Wo  = (const float*)d_in[8];
    const float* bo  = (const float*)d_in[9];
    const float* Wp1 = (const float*)d_in[10];
    const float* bp1 = (const float*)d_in[11];
    const float* Wp2 = (const float*)d_in[12];
    const float* bp2 = (const float*)d_in[13];
    float* out = (float*)d_out;

    GCoef co = fit_gelu_poly();

    dim3 g1(20, 16);
    k_proj<<<g1, 256>>>(x, Wq, bq, Wk, bk, Wv, bv, Wp1, bp1);

    dim3 g2(4, 64, 2);
    k_scores<<<g2, 256>>>(adj, Wp2, bp2, co);

    dim3 g4(64, 4, 2);
    k_av<<<g4, 256>>>();

    dim3 g5(4, 16);
    k_out<<<g5, 256>>>(Wo, bo, out);
}

// round 11
// speedup vs baseline: 1.5545x; 1.0362x over previous
#include <cuda_runtime.h>
#include <math.h>

typedef unsigned long long u64;
typedef unsigned int u32;
#define NN 512
#define NH 4
#define MR (2*NN)

__device__ float g_q[MR*256];
__device__ float g_k[MR*256];
__device__ float g_v[MR*256];
__device__ float g_a[MR*256];
__device__ float g_b[MR*256];
__device__ __align__(16) float g_attn[(size_t)2*NH*NN*NN];  // [b][h][i][j]
__device__ float g_ctx[MR*256];

struct GCoef { float c[9]; };

__device__ __forceinline__ u64 pk(float lo, float hi) {
    u64 r; asm("mov.b64 %0,{%1,%2};" : "=l"(r) : "f"(lo), "f"(hi)); return r;
}
__device__ __forceinline__ void upk(u64 v, float& lo, float& hi) {
    asm("mov.b64 {%0,%1},%2;" : "=f"(lo), "=f"(hi) : "l"(v));
}
__device__ __forceinline__ u64 f2add(u64 a, u64 b) {
    u64 d; asm("add.rn.f32x2 %0,%1,%2;" : "=l"(d) : "l"(a), "l"(b)); return d;
}
__device__ __forceinline__ u64 f2fma(u64 a, u64 b, u64 c) {
    u64 d; asm("fma.rn.f32x2 %0,%1,%2,%3;" : "=l"(d) : "l"(a), "l"(b), "l"(c)); return d;
}
__device__ __forceinline__ void cpa16(u32 dst, const void* src) {
    asm volatile("cp.async.ca.shared.global [%0], [%1], 16;" :: "r"(dst), "l"(src));
}

// ---- 64x64 GEMM, K=256, 256 thr, 4x4/thread, FMA2, reg-double-buffered ----
__device__ __forceinline__ void gemm64(
    const float* __restrict__ A, const float* __restrict__ W,
    const float* __restrict__ bias, float* __restrict__ C,
    int m0, int n0)
{
    __shared__ __align__(16) float As[2][16][68];
    __shared__ __align__(16) float Ws[2][16][68];
    int tid = threadIdx.x, tx = tid & 15, ty = tid >> 4;
    u64 acc[4][2] = {};

    int ar = tid >> 2, ac = (tid & 3) * 4;
    int wk = tid >> 4, wn = (tid & 15) * 4;

    float4 pA = *(const float4*)&A[(m0 + ar) * 256 + ac];
    float4 pW = *(const float4*)&W[wk * 256 + n0 + wn];

    int buf = 0;
    for (int t = 0; t < 16; t++) {
        As[buf][ac+0][ar] = pA.x; As[buf][ac+1][ar] = pA.y;
        As[buf][ac+2][ar] = pA.z; As[buf][ac+3][ar] = pA.w;
        *(float4*)&Ws[buf][wk][wn] = pW;
        __syncthreads();
        if (t < 15) {
            int k0 = (t + 1) * 16;
            pA = *(const float4*)&A[(m0 + ar) * 256 + k0 + ac];
            pW = *(const float4*)&W[(k0 + wk) * 256 + n0 + wn];
        }
        #pragma unroll
        for (int kk = 0; kk < 16; kk++) {
            float4 ra = *(const float4*)&As[buf][kk][ty * 4];
            ulonglong2 wv = *(const ulonglong2*)&Ws[buf][kk][tx * 4];
            u64 r0 = pk(ra.x, ra.x), r1 = pk(ra.y, ra.y);
            u64 r2 = pk(ra.z, ra.z), r3 = pk(ra.w, ra.w);
            acc[0][0] = f2fma(r0, wv.x, acc[0][0]);
            acc[0][1] = f2fma(r0, wv.y, acc[0][1]);
            acc[1][0] = f2fma(r1, wv.x, acc[1][0]);
            acc[1][1] = f2fma(r1, wv.y, acc[1][1]);
            acc[2][0] = f2fma(r2, wv.x, acc[2][0]);
            acc[2][1] = f2fma(r2, wv.y, acc[2][1]);
            acc[3][0] = f2fma(r3, wv.x, acc[3][0]);
            acc[3][1] = f2fma(r3, wv.y, acc[3][1]);
        }
        buf ^= 1;
    }
    int n = n0 + tx * 4;
    float b0 = 0.f, b1 = 0.f, b2 = 0.f, b3 = 0.f;
    if (bias) { b0 = bias[n]; b1 = bias[n+1]; b2 = bias[n+2]; b3 = bias[n+3]; }
    #pragma unroll
    for (int i = 0; i < 4; i++) {
        float o0,o1,o2,o3;
        upk(acc[i][0], o0, o1); upk(acc[i][1], o2, o3);
        *(float4*)&C[(m0 + ty*4 + i) * 256 + n] =
            make_float4(o0 + b0, o1 + b1, o2 + b2, o3 + b3);
    }
}

// ---- 32x64 GEMM (k_out: doubles grid to fill the chip) ----
__device__ __forceinline__ void gemm32(
    const float* __restrict__ A, const float* __restrict__ W,
    const float* __restrict__ bias, float* __restrict__ C,
    int m0, int n0)
{
    __shared__ __align__(16) float As[2][16][36];
    __shared__ __align__(16) float Ws[2][16][68];
    int tid = threadIdx.x, tx = tid & 15, ty = tid >> 4;
    u64 acc[2][2] = {};

    int ar = tid >> 3, ac = (tid & 7) * 2;
    int wk = tid >> 4, wn = (tid & 15) * 4;

    float2 pA = *(const float2*)&A[(m0 + ar) * 256 + ac];
    float4 pW = *(const float4*)&W[wk * 256 + n0 + wn];

    int buf = 0;
    for (int t = 0; t < 16; t++) {
        As[buf][ac+0][ar] = pA.x; As[buf][ac+1][ar] = pA.y;
        *(float4*)&Ws[buf][wk][wn] = pW;
        __syncthreads();
        if (t < 15) {
            int k0 = (t + 1) * 16;
            pA = *(const float2*)&A[(m0 + ar) * 256 + k0 + ac];
            pW = *(const float4*)&W[(k0 + wk) * 256 + n0 + wn];
        }
        #pragma unroll
        for (int kk = 0; kk < 16; kk++) {
            float2 ra = *(const float2*)&As[buf][kk][ty * 2];
            ulonglong2 wv = *(const ulonglong2*)&Ws[buf][kk][tx * 4];
            u64 r0 = pk(ra.x, ra.x), r1 = pk(ra.y, ra.y);
            acc[0][0] = f2fma(r0, wv.x, acc[0][0]);
            acc[0][1] = f2fma(r0, wv.y, acc[0][1]);
            acc[1][0] = f2fma(r1, wv.x, acc[1][0]);
            acc[1][1] = f2fma(r1, wv.y, acc[1][1]);
        }
        buf ^= 1;
    }
    int n = n0 + tx * 4;
    float b0 = 0.f, b1 = 0.f, b2 = 0.f, b3 = 0.f;
    if (bias) { b0 = bias[n]; b1 = bias[n+1]; b2 = bias[n+2]; b3 = bias[n+3]; }
    #pragma unroll
    for (int i = 0; i < 2; i++) {
        float o0,o1,o2,o3;
        upk(acc[i][0], o0, o1); upk(acc[i][1], o2, o3);
        *(float4*)&C[(m0 + ty*2 + i) * 256 + n] =
            make_float4(o0 + b0, o1 + b1, o2 + b2, o3 + b3);
    }
}

__global__ __launch_bounds__(256) void k_proj(
    const float* __restrict__ x,
    const float* __restrict__ Wq, const float* __restrict__ bq,
    const float* __restrict__ Wk, const float* __restrict__ bk,
    const float* __restrict__ Wv, const float* __restrict__ bv,
    const float* __restrict__ Wp1, const float* __restrict__ bp1)
{
    int bn = blockIdx.x;
    int seg = bn >> 2, n0 = (bn & 3) * 64;
    const float* W; const float* bias; float* C;
    switch (seg) {
        case 0: W = Wq; bias = bq; C = g_q; break;
        case 1: W = Wk; bias = bk; C = g_k; break;
        case 2: W = Wv; bias = bv; C = g_v; break;
        case 3: W = Wp1; bias = nullptr; C = g_a; break;
        default: W = Wp1 + 256*256; bias = bp1; C = g_b; break;  // bp1 folded
    }
    gemm64(x, W, bias, C, blockIdx.y * 64, n0);
}

// ------- K2: fused pair scores (cp.async tiles + 6-shfl epilogue, deg-8) -------
__global__ __launch_bounds__(256, 2) void k_scores(
    const int* __restrict__ adj, const float* __restrict__ Wp2,
    const float* __restrict__ bp2, GCoef co)
{
    int b = blockIdx.z, i0 = blockIdx.y * 8, j0base = blockIdx.x * 128;
    int tid = threadIdx.x, lane = tid & 31, w = tid >> 5;
    int h = lane >> 3;

    __shared__ __align__(16) float sA[8][256], sQ[8][256];
    __shared__ __align__(16) float sB[2][8][256], sK[2][8][256];
    __shared__ int sM[8][128];

    u32 sBu = (u32)__cvta_generic_to_shared(sB);
    u32 sKu = (u32)__cvta_generic_to_shared(sK);
    const char* gB0 = (const char*)(g_b + (b * NN + j0base) * 256);
    const char* gK0 = (const char*)(g_k + (b * NN + j0base) * 256);
    int cpo = tid * 16;

    auto PREF = [&](int tile, int buf) {
        cpa16(sBu + buf*8192 + cpo,        gB0 + tile*8192 + cpo);
        cpa16(sBu + buf*8192 + cpo + 4096, gB0 + tile*8192 + cpo + 4096);
        cpa16(sKu + buf*8192 + cpo,        gK0 + tile*8192 + cpo);
        cpa16(sKu + buf*8192 + cpo + 4096, gK0 + tile*8192 + cpo + 4096);
        asm volatile("cp.async.commit_group;");
    };
    PREF(0, 0); PREF(1, 1);

    u64 C[9];
    #pragma unroll
    for (int kk = 0; kk < 9; kk++) C[kk] = pk(co.c[kk], co.c[kk]);
    const u64 K3 = pk(1.0f/3.0f, 1.0f/3.0f);
    const u64 KM1 = pk(-1.0f, -1.0f);
    const u64 KABS = 0x7FFFFFFF7FFFFFFFull;

    u64 w2[4][4];
    {
        int cb = lane * 8;
        #pragma unroll
        for (int p = 0; p < 4; p++) {
            float4 wa = *(const float4*)&Wp2[(cb + 2*p) * 4];
            float4 wb = *(const float4*)&Wp2[(cb + 2*p + 1) * 4];
            w2[p][0] = pk(0.5f*wa.x, 0.5f*wb.x);
            w2[p][1] = pk(0.5f*wa.y, 0.5f*wb.y);
            w2[p][2] = pk(0.5f*wa.z, 0.5f*wb.z);
            w2[p][3] = pk(0.5f*wa.w, 0.5f*wb.w);
        }
    }
    float myb = bp2[h];
    bool up = lane >= 16;
    bool g1sel = (lane & 8) != 0;

    const float* aptr = g_a + (b * NN + i0) * 256;
    const float* qptr = g_q + (b * NN + i0) * 256;
    #pragma unroll
    for (int t = 0; t < 2; t++) {
        int idx = tid + t * 256;
        ((float4*)sA)[idx] = ((const float4*)aptr)[idx];
        ((float4*)sQ)[idx] = ((const float4*)qptr)[idx];
    }
    #pragma unroll
    for (int t = 0; t < 4; t++) {
        int idx = tid + t * 256;
        sM[idx >> 7][idx & 127] = adj[(i0 + (idx >> 7)) * NN + j0base + (idx & 127)];
    }

    for (int jc = 0; jc < 16; jc++) {
        if (jc < 15) asm volatile("cp.async.wait_group 1;");
        else         asm volatile("cp.async.wait_group 0;");
        __syncthreads();
        int buf = jc & 1;
        int j = j0base + jc * 8 + w;

        u64 bbp[4], kvp[4];
        {
            ulonglong2 x0 = *(const ulonglong2*)&sB[buf][w][lane*8];
            ulonglong2 x1 = *(const ulonglong2*)&sB[buf][w][lane*8+4];
            bbp[0]=x0.x; bbp[1]=x0.y; bbp[2]=x1.x; bbp[3]=x1.y;
            ulonglong2 y0 = *(const ulonglong2*)&sK[buf][w][lane*8];
            ulonglong2 y1 = *(const ulonglong2*)&sK[buf][w][lane*8+4];
            kvp[0]=y0.x; kvp[1]=y0.y; kvp[2]=y1.x; kvp[3]=y1.y;
        }

        #pragma unroll
        for (int il = 0; il < 8; il++) {
            int mval = sM[il][jc * 8 + w];
            int i = i0 + il;
            float* outp = &g_attn[((size_t)(b * NH) * NN + i) * NN + j];
            if (mval == 0) {
                if ((lane & 7) == 0) outp[(size_t)h * NN * NN] = -1e9f;
                continue;
            }
            u64 aA[4], qA[4];
            {
                ulonglong2 x0 = *(const ulonglong2*)&sA[il][lane*8];
                ulonglong2 x1 = *(const ulonglong2*)&sA[il][lane*8+4];
                aA[0]=x0.x; aA[1]=x0.y; aA[2]=x1.x; aA[3]=x1.y;
                ulonglong2 y0 = *(const ulonglong2*)&sQ[il][lane*8];
                ulonglong2 y1 = *(const ulonglong2*)&sQ[il][lane*8+4];
                qA[0]=y0.x; qA[1]=y0.y; qA[2]=y1.x; qA[3]=y1.y;
            }
            u64 aw0=0, aw1=0, aw2=0, aw3=0, qk=0;
            #pragma unroll
            for (int p = 0; p < 4; p++) {
                u64 t = f2add(aA[p], bbp[p]);
                u64 m = t & KABS;
                u64 wv = f2fma(m, K3, KM1);
                u64 S = C[8];
                #pragma unroll
                for (int kk = 7; kk >= 0; kk--) S = f2fma(S, wv, C[kk]);
                u64 G = f2add(f2add(t, m), S);   // 2*gelu
                aw0 = f2fma(G, w2[p][0], aw0);
                aw1 = f2fma(G, w2[p][1], aw1);
                aw2 = f2fma(G, w2[p][2], aw2);
                aw3 = f2fma(G, w2[p][3], aw3);
                qk  = f2fma(qA[p], kvp[p], qk);
            }
            float r0,r1,r2,r3,x0,x1,qx,qy;
            upk(aw0,r0,x0); r0+=x0;
            upk(aw1,r1,x1); r1+=x1;
            upk(aw2,r2,x0); r2+=x0;
            upk(aw3,r3,x1); r3+=x1;
            upk(qk,qx,qy);
            float qs = (qx+qy)*0.125f;
            if (h==0) r0+=qs; else if (h==1) r1+=qs; else if (h==2) r2+=qs; else r3+=qs;

            // 6-shfl multi-value reduction
            float s1 = up ? r0 : r2;
            float t1 = up ? r1 : r3;
            s1 = __shfl_xor_sync(~0u, s1, 16);
            t1 = __shfl_xor_sync(~0u, t1, 16);
            float ra, rb;
            if (!up) { ra = r0 + s1; rb = r1 + t1; }
            else     { ra = r2 + s1; rb = r3 + t1; }
            float u8 = g1sel ? ra : rb;
            u8 = __shfl_xor_sync(~0u, u8, 8);
            float v = g1sel ? (rb + u8) : (ra + u8);
            v += __shfl_xor_sync(~0u, v, 4);
            v += __shfl_xor_sync(~0u, v, 2);
            v += __shfl_xor_sync(~0u, v, 1);
            if ((lane & 7) == 0) outp[(size_t)h * NN * NN] = v + myb;
        }
        __syncthreads();
        if (jc + 2 < 16) PREF(jc + 2, buf);
    }
}

// ---------------- fast exp (no MUFU) ----------------
__device__ __forceinline__ float fexp(float x) {
    x = fmaxf(x, -87.0f);
    float y = x * 1.4426950408889634f;
    float f = floorf(y);
    float r = y - f;
    float p = 1.5403530e-4f;
    p = fmaf(p, r, 1.3333558e-3f);
    p = fmaf(p, r, 9.6181291e-3f);
    p = fmaf(p, r, 5.5504109e-2f);
    p = fmaf(p, r, 2.4022651e-1f);
    p = fmaf(p, r, 6.9314718e-1f);
    p = fmaf(p, r, 1.0f);
    return __int_as_float(__float_as_int(p) + (((int)f) << 23));
}

// ---------------- K3: fused softmax + attn@v (batched V loads) ----------------
__global__ __launch_bounds__(256) void k_av()
{
    int b = blockIdx.z, h = blockIdx.y, i0 = blockIdx.x * 8;
    int tid = threadIdx.x, w = tid >> 5, lane = tid & 31;

    __shared__ __align__(16) float sP[8][512];
    __shared__ __align__(16) float sRed[8][8][64];
    __shared__ float sInv[8];

    {
        const float* arow = g_attn + (((size_t)(b*NH+h))*NN + (i0+w))*NN;
        float4 vv[4];
        float mx = -3.4e38f;
        #pragma unroll
        for (int t = 0; t < 4; t++) {
            vv[t] = ((const float4*)arow)[lane + 32*t];
            mx = fmaxf(mx, fmaxf(fmaxf(vv[t].x,vv[t].y), fmaxf(vv[t].z,vv[t].w)));
        }
        #pragma unroll
        for (int o = 16; o; o >>= 1) mx = fmaxf(mx, __shfl_xor_sync(~0u, mx, o));
        float s = 0.f;
        #pragma unroll
        for (int t = 0; t < 4; t++) {
            vv[t].x = fexp(vv[t].x - mx); vv[t].y = fexp(vv[t].y - mx);
            vv[t].z = fexp(vv[t].z - mx); vv[t].w = fexp(vv[t].w - mx);
            s += vv[t].x + vv[t].y + vv[t].z + vv[t].w;
            *(float4*)&sP[w][lane*4 + t*128] = vv[t];
        }
        #pragma unroll
        for (int o = 16; o; o >>= 1) s += __shfl_xor_sync(~0u, s, o);
        if (lane == 0) sInv[w] = 1.0f / s;
    }
    __syncthreads();

    float2 acc[8] = {};
    const float2* vp = (const float2*)&g_v[(b*NN + w*64)*256 + h*64 + lane*2];
    #pragma unroll 2
    for (int jj = 0; jj < 64; jj += 8) {
        float2 v[8];
        #pragma unroll
        for (int u = 0; u < 8; u++) v[u] = vp[(size_t)(jj + u) * 128];
        #pragma unroll
        for (int i = 0; i < 8; i++) {
            float4 pa = *(const float4*)&sP[i][w*64 + jj];
            float4 pb = *(const float4*)&sP[i][w*64 + jj + 4];
            acc[i].x = fmaf(pa.x, v[0].x, acc[i].x); acc[i].y = fmaf(pa.x, v[0].y, acc[i].y);
            acc[i].x = fmaf(pa.y, v[1].x, acc[i].x); acc[i].y = fmaf(pa.y, v[1].y, acc[i].y);
            acc[i].x = fmaf(pa.z, v[2].x, acc[i].x); acc[i].y = fmaf(pa.z, v[2].y, acc[i].y);
            acc[i].x = fmaf(pa.w, v[3].x, acc[i].x); acc[i].y = fmaf(pa.w, v[3].y, acc[i].y);
            acc[i].x = fmaf(pb.x, v[4].x, acc[i].x); acc[i].y = fmaf(pb.x, v[4].y, acc[i].y);
            acc[i].x = fmaf(pb.y, v[5].x, acc[i].x); acc[i].y = fmaf(pb.y, v[5].y, acc[i].y);
            acc[i].x = fmaf(pb.z, v[6].x, acc[i].x); acc[i].y = fmaf(pb.z, v[6].y, acc[i].y);
            acc[i].x = fmaf(pb.w, v[7].x, acc[i].x); acc[i].y = fmaf(pb.w, v[7].y, acc[i].y);
        }
    }
    #pragma unroll
    for (int i = 0; i < 8; i++)
        *(float2*)&sRed[w][i][lane*2] = acc[i];
    __syncthreads();

    int i = tid >> 5, d = (tid * 2) & 63;
    float sx = 0.f, sy = 0.f;
    #pragma unroll
    for (int ww = 0; ww < 8; ww++) {
        float2 t = *(const float2*)&sRed[ww][i][d];
        sx += t.x; sy += t.y;
    }
    float inv = sInv[i];
    *(float2*)&g_ctx[(b*NN + i0 + i)*256 + h*64 + d] = make_float2(sx*inv, sy*inv);
}

__global__ __launch_bounds__(256) void k_out(
    const float* __restrict__ Wo, const float* __restrict__ bo,
    float* __restrict__ out)
{
    gemm32(g_ctx, Wo, bo, out, blockIdx.y * 32, blockIdx.x * 64);
}

// ---- host: Chebyshev fit of S(m) = -m*erfc(m/sqrt2), m in [0,6], deg 8 ----
static GCoef fit_gelu_poly() {
    const int DEG = 8, M = 64;
    double cc[DEG+1], fv[M];
    for (int j = 0; j < M; j++) {
        double xx = cos(M_PI * (j + 0.5) / M);
        double m = 3.0 * (xx + 1.0);
        fv[j] = -m * erfc(m * 0.7071067811865476);
    }
    for (int k = 0; k <= DEG; k++) {
        double s = 0;
        for (int j = 0; j < M; j++) s += fv[j] * cos(k * M_PI * (j + 0.5) / M);
        cc[k] = s * ((k == 0 ? 1.0 : 2.0) / M);
    }
    double mono[DEG+1] = {0}, Tm2[DEG+1] = {0}, Tm1[DEG+1] = {0}, Tk[DEG+1];
    Tm2[0] = 1.0; Tm1[1] = 1.0;
    mono[0] += cc[0];
    mono[1] += cc[1];
    for (int k = 2; k <= DEG; k++) {
        for (int i = 0; i <= DEG; i++) Tk[i] = -Tm2[i] + 2.0 * (i > 0 ? Tm1[i-1] : 0.0);
        for (int i = 0; i <= DEG; i++) mono[i] += cc[k] * Tk[i];
        for (int i = 0; i <= DEG; i++) { Tm2[i] = Tm1[i]; Tm1[i] = Tk[i]; }
    }
    GCoef g;
    for (int i = 0; i <= DEG; i++) g.c[i] = (float)mono[i];
    return g;
}

extern "C" void kernel_launch(void* const* d_in, const int* in_sizes, int n_in,
                              void* d_out, int out_size)
{
    const float* x   = (const float*)d_in[0];
    const int*   adj = (const int*)  d_in[1];
    const float* Wq  = (const float*)d_in[2];
    const float* bq  = (const float*)d_in[3];
    const float* Wk  = (const float*)d_in[4];
    const float* bk  = (const float*)d_in[5];
    const float* Wv  = (const float*)d_in[6];
    const float* bv  = (const float*)d_in[7];
    const float* Wo  = (const float*)d_in[8];
    const float* bo  = (const float*)d_in[9];
    const float* Wp1 = (const float*)d_in[10];
    const float* bp1 = (const float*)d_in[11];
    const float* Wp2 = (const float*)d_in[12];
    const float* bp2 = (const float*)d_in[13];
    float* out = (float*)d_out;

    GCoef co = fit_gelu_poly();

    dim3 g1(20, 16);
    k_proj<<<g1, 256>>>(x, Wq, bq, Wk, bk, Wv, bv, Wp1, bp1);

    dim3 g2(4, 64, 2);
    k_scores<<<g2, 256>>>(adj, Wp2, bp2, co);

    dim3 g4(64, 4, 2);
    k_av<<<g4, 256>>>();

    dim3 g5(4, 32);
    k_out<<<g5, 256>>>(Wo, bo, out);
}

// round 12
// speedup vs baseline: 1.8241x; 1.1734x over previous
#include <cuda_runtime.h>
#include <math.h>

typedef unsigned long long u64;
typedef unsigned int u32;
#define NN 512
#define NH 4
#define MR (2*NN)

__device__ float g_q[MR*256];
__device__ float g_k[MR*256];
__device__ float g_v[MR*256];
__device__ float g_a[MR*256];
__device__ float g_b[MR*256];
__device__ __align__(16) float g_attn[(size_t)2*NH*NN*NN];  // [b][h][i][j]
__device__ float g_ctx[MR*256];

struct GCoef { float c[9]; };

__device__ __forceinline__ u64 pk(float lo, float hi) {
    u64 r; asm("mov.b64 %0,{%1,%2};" : "=l"(r) : "f"(lo), "f"(hi)); return r;
}
__device__ __forceinline__ void upk(u64 v, float& lo, float& hi) {
    asm("mov.b64 {%0,%1},%2;" : "=f"(lo), "=f"(hi) : "l"(v));
}
__device__ __forceinline__ u64 f2add(u64 a, u64 b) {
    u64 d; asm("add.rn.f32x2 %0,%1,%2;" : "=l"(d) : "l"(a), "l"(b)); return d;
}
__device__ __forceinline__ u64 f2fma(u64 a, u64 b, u64 c) {
    u64 d; asm("fma.rn.f32x2 %0,%1,%2,%3;" : "=l"(d) : "l"(a), "l"(b), "l"(c)); return d;
}

// ---- 64x64 GEMM, K=256, 256 thr, 4x4/thread, FMA2, reg-double-buffered ----
__device__ __forceinline__ void gemm64(
    const float* __restrict__ A, const float* __restrict__ W,
    const float* __restrict__ bias, float* __restrict__ C,
    int m0, int n0)
{
    __shared__ __align__(16) float As[2][16][68];
    __shared__ __align__(16) float Ws[2][16][68];
    int tid = threadIdx.x, tx = tid & 15, ty = tid >> 4;
    u64 acc[4][2] = {};

    int ar = tid >> 2, ac = (tid & 3) * 4;
    int wk = tid >> 4, wn = (tid & 15) * 4;

    float4 pA = *(const float4*)&A[(m0 + ar) * 256 + ac];
    float4 pW = *(const float4*)&W[wk * 256 + n0 + wn];

    int buf = 0;
    for (int t = 0; t < 16; t++) {
        As[buf][ac+0][ar] = pA.x; As[buf][ac+1][ar] = pA.y;
        As[buf][ac+2][ar] = pA.z; As[buf][ac+3][ar] = pA.w;
        *(float4*)&Ws[buf][wk][wn] = pW;
        __syncthreads();
        if (t < 15) {
            int k0 = (t + 1) * 16;
            pA = *(const float4*)&A[(m0 + ar) * 256 + k0 + ac];
            pW = *(const float4*)&W[(k0 + wk) * 256 + n0 + wn];
        }
        #pragma unroll
        for (int kk = 0; kk < 16; kk++) {
            float4 ra = *(const float4*)&As[buf][kk][ty * 4];
            ulonglong2 wv = *(const ulonglong2*)&Ws[buf][kk][tx * 4];
            u64 r0 = pk(ra.x, ra.x), r1 = pk(ra.y, ra.y);
            u64 r2 = pk(ra.z, ra.z), r3 = pk(ra.w, ra.w);
            acc[0][0] = f2fma(r0, wv.x, acc[0][0]);
            acc[0][1] = f2fma(r0, wv.y, acc[0][1]);
            acc[1][0] = f2fma(r1, wv.x, acc[1][0]);
            acc[1][1] = f2fma(r1, wv.y, acc[1][1]);
            acc[2][0] = f2fma(r2, wv.x, acc[2][0]);
            acc[2][1] = f2fma(r2, wv.y, acc[2][1]);
            acc[3][0] = f2fma(r3, wv.x, acc[3][0]);
            acc[3][1] = f2fma(r3, wv.y, acc[3][1]);
        }
        buf ^= 1;
    }
    int n = n0 + tx * 4;
    float b0 = 0.f, b1 = 0.f, b2 = 0.f, b3 = 0.f;
    if (bias) { b0 = bias[n]; b1 = bias[n+1]; b2 = bias[n+2]; b3 = bias[n+3]; }
    #pragma unroll
    for (int i = 0; i < 4; i++) {
        float o0,o1,o2,o3;
        upk(acc[i][0], o0, o1); upk(acc[i][1], o2, o3);
        *(float4*)&C[(m0 + ty*4 + i) * 256 + n] =
            make_float4(o0 + b0, o1 + b1, o2 + b2, o3 + b3);
    }
}

// ---- 32x64 GEMM (k_out) ----
__device__ __forceinline__ void gemm32(
    const float* __restrict__ A, const float* __restrict__ W,
    const float* __restrict__ bias, float* __restrict__ C,
    int m0, int n0)
{
    __shared__ __align__(16) float As[2][16][36];
    __shared__ __align__(16) float Ws[2][16][68];
    int tid = threadIdx.x, tx = tid & 15, ty = tid >> 4;
    u64 acc[2][2] = {};

    int ar = tid >> 3, ac = (tid & 7) * 2;
    int wk = tid >> 4, wn = (tid & 15) * 4;

    float2 pA = *(const float2*)&A[(m0 + ar) * 256 + ac];
    float4 pW = *(const float4*)&W[wk * 256 + n0 + wn];

    int buf = 0;
    for (int t = 0; t < 16; t++) {
        As[buf][ac+0][ar] = pA.x; As[buf][ac+1][ar] = pA.y;
        *(float4*)&Ws[buf][wk][wn] = pW;
        __syncthreads();
        if (t < 15) {
            int k0 = (t + 1) * 16;
            pA = *(const float2*)&A[(m0 + ar) * 256 + k0 + ac];
            pW = *(const float4*)&W[(k0 + wk) * 256 + n0 + wn];
        }
        #pragma unroll
        for (int kk = 0; kk < 16; kk++) {
            float2 ra = *(const float2*)&As[buf][kk][ty * 2];
            ulonglong2 wv = *(const ulonglong2*)&Ws[buf][kk][tx * 4];
            u64 r0 = pk(ra.x, ra.x), r1 = pk(ra.y, ra.y);
            acc[0][0] = f2fma(r0, wv.x, acc[0][0]);
            acc[0][1] = f2fma(r0, wv.y, acc[0][1]);
            acc[1][0] = f2fma(r1, wv.x, acc[1][0]);
            acc[1][1] = f2fma(r1, wv.y, acc[1][1]);
        }
        buf ^= 1;
    }
    int n = n0 + tx * 4;
    float b0 = 0.f, b1 = 0.f, b2 = 0.f, b3 = 0.f;
    if (bias) { b0 = bias[n]; b1 = bias[n+1]; b2 = bias[n+2]; b3 = bias[n+3]; }
    #pragma unroll
    for (int i = 0; i < 2; i++) {
        float o0,o1,o2,o3;
        upk(acc[i][0], o0, o1); upk(acc[i][1], o2, o3);
        *(float4*)&C[(m0 + ty*2 + i) * 256 + n] =
            make_float4(o0 + b0, o1 + b1, o2 + b2, o3 + b3);
    }
}

__global__ __launch_bounds__(256) void k_proj(
    const float* __restrict__ x,
    const float* __restrict__ Wq, const float* __restrict__ bq,
    const float* __restrict__ Wk, const float* __restrict__ bk,
    const float* __restrict__ Wv, const float* __restrict__ bv,
    const float* __restrict__ Wp1, const float* __restrict__ bp1)
{
    int bn = blockIdx.x;
    int seg = bn >> 2, n0 = (bn & 3) * 64;
    const float* W; const float* bias; float* C;
    switch (seg) {
        case 0: W = Wq; bias = bq; C = g_q; break;
        case 1: W = Wk; bias = bk; C = g_k; break;
        case 2: W = Wv; bias = bv; C = g_v; break;
        case 3: W = Wp1; bias = nullptr; C = g_a; break;
        default: W = Wp1 + 256*256; bias = bp1; C = g_b; break;  // bp1 folded
    }
    gemm64(x, W, bias, C, blockIdx.y * 64, n0);
}

// ------- K2: fused pair scores, BARRIER-FREE (per-warp global row loads) -------
__global__ __launch_bounds__(256, 2) void k_scores(
    const int* __restrict__ adj, const float* __restrict__ Wp2,
    const float* __restrict__ bp2, GCoef co)
{
    int b = blockIdx.z, i0 = blockIdx.y * 8, j0base = blockIdx.x * 128;
    int tid = threadIdx.x, lane = tid & 31, w = tid >> 5;
    int h = lane >> 3;

    __shared__ __align__(16) float sA[8][256], sQ[8][256];
    __shared__ int sM[8][128];

    u64 C[9];
    #pragma unroll
    for (int kk = 0; kk < 9; kk++) C[kk] = pk(co.c[kk], co.c[kk]);
    const u64 K3 = pk(1.0f/3.0f, 1.0f/3.0f);
    const u64 KM1 = pk(-1.0f, -1.0f);
    const u64 KABS = 0x7FFFFFFF7FFFFFFFull;

    u64 w2[4][4];
    {
        int cb = lane * 8;
        #pragma unroll
        for (int p = 0; p < 4; p++) {
            float4 wa = *(const float4*)&Wp2[(cb + 2*p) * 4];
            float4 wb = *(const float4*)&Wp2[(cb + 2*p + 1) * 4];
            w2[p][0] = pk(0.5f*wa.x, 0.5f*wb.x);
            w2[p][1] = pk(0.5f*wa.y, 0.5f*wb.y);
            w2[p][2] = pk(0.5f*wa.z, 0.5f*wb.z);
            w2[p][3] = pk(0.5f*wa.w, 0.5f*wb.w);
        }
    }
    float myb = bp2[h];
    bool up = lane >= 16;
    bool g1sel = (lane & 8) != 0;

    const float* aptr = g_a + (b * NN + i0) * 256;
    const float* qptr = g_q + (b * NN + i0) * 256;
    #pragma unroll
    for (int t = 0; t < 2; t++) {
        int idx = tid + t * 256;
        ((float4*)sA)[idx] = ((const float4*)aptr)[idx];
        ((float4*)sQ)[idx] = ((const float4*)qptr)[idx];
    }
    #pragma unroll
    for (int t = 0; t < 4; t++) {
        int idx = tid + t * 256;
        sM[idx >> 7][idx & 127] = adj[(i0 + (idx >> 7)) * NN + j0base + (idx & 127)];
    }
    __syncthreads();    // ONLY barrier: sA/sQ/sM ready; warps free-run after this

    for (int jc = 0; jc < 16; jc++) {
        int j = j0base + jc * 8 + w;

        // this warp's own B/K row straight from L2 (coalesced 1KB per warp)
        u64 bbp[4], kvp[4];
        {
            const ulonglong2* bp = (const ulonglong2*)&g_b[(b * NN + j) * 256 + lane * 8];
            const ulonglong2* kp = (const ulonglong2*)&g_k[(b * NN + j) * 256 + lane * 8];
            ulonglong2 x0 = bp[0], x1 = bp[1];
            ulonglong2 y0 = kp[0], y1 = kp[1];
            bbp[0]=x0.x; bbp[1]=x0.y; bbp[2]=x1.x; bbp[3]=x1.y;
            kvp[0]=y0.x; kvp[1]=y0.y; kvp[2]=y1.x; kvp[3]=y1.y;
        }

        #pragma unroll
        for (int il = 0; il < 8; il++) {
            int mval = sM[il][jc * 8 + w];
            int i = i0 + il;
            float* outp = &g_attn[((size_t)(b * NH) * NN + i) * NN + j];
            if (mval == 0) {
                if ((lane & 7) == 0) outp[(size_t)h * NN * NN] = -1e9f;
                continue;
            }
            u64 aA[4], qA[4];
            {
                ulonglong2 x0 = *(const ulonglong2*)&sA[il][lane*8];
                ulonglong2 x1 = *(const ulonglong2*)&sA[il][lane*8+4];
                aA[0]=x0.x; aA[1]=x0.y; aA[2]=x1.x; aA[3]=x1.y;
                ulonglong2 y0 = *(const ulonglong2*)&sQ[il][lane*8];
                ulonglong2 y1 = *(const ulonglong2*)&sQ[il][lane*8+4];
                qA[0]=y0.x; qA[1]=y0.y; qA[2]=y1.x; qA[3]=y1.y;
            }
            u64 aw0=0, aw1=0, aw2=0, aw3=0, qk=0;
            #pragma unroll
            for (int p = 0; p < 4; p++) {
                u64 t = f2add(aA[p], bbp[p]);
                u64 m = t & KABS;
                u64 wv = f2fma(m, K3, KM1);
                u64 S = C[8];
                #pragma unroll
                for (int kk = 7; kk >= 0; kk--) S = f2fma(S, wv, C[kk]);
                u64 G = f2add(f2add(t, m), S);   // 2*gelu
                aw0 = f2fma(G, w2[p][0], aw0);
                aw1 = f2fma(G, w2[p][1], aw1);
                aw2 = f2fma(G, w2[p][2], aw2);
                aw3 = f2fma(G, w2[p][3], aw3);
                qk  = f2fma(qA[p], kvp[p], qk);
            }
            float r0,r1,r2,r3,x0,x1,qx,qy;
            upk(aw0,r0,x0); r0+=x0;
            upk(aw1,r1,x1); r1+=x1;
            upk(aw2,r2,x0); r2+=x0;
            upk(aw3,r3,x1); r3+=x1;
            upk(qk,qx,qy);
            float qs = (qx+qy)*0.125f;
            if (h==0) r0+=qs; else if (h==1) r1+=qs; else if (h==2) r2+=qs; else r3+=qs;

            // 6-shfl multi-value reduction
            float s1 = up ? r0 : r2;
            float t1 = up ? r1 : r3;
            s1 = __shfl_xor_sync(~0u, s1, 16);
            t1 = __shfl_xor_sync(~0u, t1, 16);
            float ra, rb;
            if (!up) { ra = r0 + s1; rb = r1 + t1; }
            else     { ra = r2 + s1; rb = r3 + t1; }
            float u8 = g1sel ? ra : rb;
            u8 = __shfl_xor_sync(~0u, u8, 8);
            float v = g1sel ? (rb + u8) : (ra + u8);
            v += __shfl_xor_sync(~0u, v, 4);
            v += __shfl_xor_sync(~0u, v, 2);
            v += __shfl_xor_sync(~0u, v, 1);
            if ((lane & 7) == 0) outp[(size_t)h * NN * NN] = v + myb;
        }
    }
}

// ---------------- fast exp (no MUFU) ----------------
__device__ __forceinline__ float fexp(float x) {
    x = fmaxf(x, -87.0f);
    float y = x * 1.4426950408889634f;
    float f = floorf(y);
    float r = y - f;
    float p = 1.5403530e-4f;
    p = fmaf(p, r, 1.3333558e-3f);
    p = fmaf(p, r, 9.6181291e-3f);
    p = fmaf(p, r, 5.5504109e-2f);
    p = fmaf(p, r, 2.4022651e-1f);
    p = fmaf(p, r, 6.9314718e-1f);
    p = fmaf(p, r, 1.0f);
    return __int_as_float(__float_as_int(p) + (((int)f) << 23));
}

// ---------------- K3: fused softmax + attn@v (batched V loads) ----------------
__global__ __launch_bounds__(256) void k_av()
{
    int b = blockIdx.z, h = blockIdx.y, i0 = blockIdx.x * 8;
    int tid = threadIdx.x, w = tid >> 5, lane = tid & 31;

    __shared__ __align__(16) float sP[8][512];
    __shared__ __align__(16) float sRed[8][8][64];
    __shared__ float sInv[8];

    {
        const float* arow = g_attn + (((size_t)(b*NH+h))*NN + (i0+w))*NN;
        float4 vv[4];
        float mx = -3.4e38f;
        #pragma unroll
        for (int t = 0; t < 4; t++) {
            vv[t] = ((const float4*)arow)[lane + 32*t];
            mx = fmaxf(mx, fmaxf(fmaxf(vv[t].x,vv[t].y), fmaxf(vv[t].z,vv[t].w)));
        }
        #pragma unroll
        for (int o = 16; o; o >>= 1) mx = fmaxf(mx, __shfl_xor_sync(~0u, mx, o));
        float s = 0.f;
        #pragma unroll
        for (int t = 0; t < 4; t++) {
            vv[t].x = fexp(vv[t].x - mx); vv[t].y = fexp(vv[t].y - mx);
            vv[t].z = fexp(vv[t].z - mx); vv[t].w = fexp(vv[t].w - mx);
            s += vv[t].x + vv[t].y + vv[t].z + vv[t].w;
            *(float4*)&sP[w][lane*4 + t*128] = vv[t];
        }
        #pragma unroll
        for (int o = 16; o; o >>= 1) s += __shfl_xor_sync(~0u, s, o);
        if (lane == 0) sInv[w] = 1.0f / s;
    }
    __syncthreads();

    float2 acc[8] = {};
    const float2* vp = (const float2*)&g_v[(b*NN + w*64)*256 + h*64 + lane*2];
    #pragma unroll 2
    for (int jj = 0; jj < 64; jj += 8) {
        float2 v[8];
        #pragma unroll
        for (int u = 0; u < 8; u++) v[u] = vp[(size_t)(jj + u) * 128];
        #pragma unroll
        for (int i = 0; i < 8; i++) {
            float4 pa = *(const float4*)&sP[i][w*64 + jj];
            float4 pb = *(const float4*)&sP[i][w*64 + jj + 4];
            acc[i].x = fmaf(pa.x, v[0].x, acc[i].x); acc[i].y = fmaf(pa.x, v[0].y, acc[i].y);
            acc[i].x = fmaf(pa.y, v[1].x, acc[i].x); acc[i].y = fmaf(pa.y, v[1].y, acc[i].y);
            acc[i].x = fmaf(pa.z, v[2].x, acc[i].x); acc[i].y = fmaf(pa.z, v[2].y, acc[i].y);
            acc[i].x = fmaf(pa.w, v[3].x, acc[i].x); acc[i].y = fmaf(pa.w, v[3].y, acc[i].y);
            acc[i].x = fmaf(pb.x, v[4].x, acc[i].x); acc[i].y = fmaf(pb.x, v[4].y, acc[i].y);
            acc[i].x = fmaf(pb.y, v[5].x, acc[i].x); acc[i].y = fmaf(pb.y, v[5].y, acc[i].y);
            acc[i].x = fmaf(pb.z, v[6].x, acc[i].x); acc[i].y = fmaf(pb.z, v[6].y, acc[i].y);
            acc[i].x = fmaf(pb.w, v[7].x, acc[i].x); acc[i].y = fmaf(pb.w, v[7].y, acc[i].y);
        }
    }
    #pragma unroll
    for (int i = 0; i < 8; i++)
        *(float2*)&sRed[w][i][lane*2] = acc[i];
    __syncthreads();

    int i = tid >> 5, d = (tid * 2) & 63;
    float sx = 0.f, sy = 0.f;
    #pragma unroll
    for (int ww = 0; ww < 8; ww++) {
        float2 t = *(const float2*)&sRed[ww][i][d];
        sx += t.x; sy += t.y;
    }
    float inv = sInv[i];
    *(float2*)&g_ctx[(b*NN + i0 + i)*256 + h*64 + d] = make_float2(sx*inv, sy*inv);
}

__global__ __launch_bounds__(256) void k_out(
    const float* __restrict__ Wo, const float* __restrict__ bo,
    float* __restrict__ out)
{
    gemm32(g_ctx, Wo, bo, out, blockIdx.y * 32, blockIdx.x * 64);
}

// ---- host: Chebyshev fit of S(m) = -m*erfc(m/sqrt2), m in [0,6], deg 8 ----
static GCoef fit_gelu_poly() {
    const int DEG = 8, M = 64;
    double cc[DEG+1], fv[M];
    for (int j = 0; j < M; j++) {
        double xx = cos(M_PI * (j + 0.5) / M);
        double m = 3.0 * (xx + 1.0);
        fv[j] = -m * erfc(m * 0.7071067811865476);
    }
    for (int k = 0; k <= DEG; k++) {
        double s = 0;
        for (int j = 0; j < M; j++) s += fv[j] * cos(k * M_PI * (j + 0.5) / M);
        cc[k] = s * ((k == 0 ? 1.0 : 2.0) / M);
    }
    double mono[DEG+1] = {0}, Tm2[DEG+1] = {0}, Tm1[DEG+1] = {0}, Tk[DEG+1];
    Tm2[0] = 1.0; Tm1[1] = 1.0;
    mono[0] += cc[0];
    mono[1] += cc[1];
    for (int k = 2; k <= DEG; k++) {
        for (int i = 0; i <= DEG; i++) Tk[i] = -Tm2[i] + 2.0 * (i > 0 ? Tm1[i-1] : 0.0);
        for (int i = 0; i <= DEG; i++) mono[i] += cc[k] * Tk[i];
        for (int i = 0; i <= DEG; i++) { Tm2[i] = Tm1[i]; Tm1[i] = Tk[i]; }
    }
    GCoef g;
    for (int i = 0; i <= DEG; i++) g.c[i] = (float)mono[i];
    return g;
}

extern "C" void kernel_launch(void* const* d_in, const int* in_sizes, int n_in,
                              void* d_out, int out_size)
{
    const float* x   = (const float*)d_in[0];
    const int*   adj = (const int*)  d_in[1];
    const float* Wq  = (const float*)d_in[2];
    const float* bq  = (const float*)d_in[3];
    const float* Wk  = (const float*)d_in[4];
    const float* bk  = (const float*)d_in[5];
    const float* Wv  = (const float*)d_in[6];
    const float* bv  = (const float*)d_in[7];
    const float* Wo  = (const float*)d_in[8];
    const float* bo  = (const float*)d_in[9];
    const float* Wp1 = (const float*)d_in[10];
    const float* bp1 = (const float*)d_in[11];
    const float* Wp2 = (const float*)d_in[12];
    const float* bp2 = (const float*)d_in[13];
    float* out = (float*)d_out;

    GCoef co = fit_gelu_poly();

    dim3 g1(20, 16);
    k_proj<<<g1, 256>>>(x, Wq, bq, Wk, bk, Wv, bv, Wp1, bp1);

    dim3 g2(4, 64, 2);
    k_scores<<<g2, 256>>>(adj, Wp2, bp2, co);

    dim3 g4(64, 4, 2);
    k_av<<<g4, 256>>>();

    dim3 g5(4, 32);
    k_out<<<g5, 256>>>(Wo, bo, out);
}